// round 10
// baseline (speedup 1.0000x reference)
#include <cuda_runtime.h>
#include <cuda_bf16.h>
#include <cuda_fp16.h>
#include <cstdint>
#include <cstddef>

#define TOK    12288
#define DMODEL 1024
#define QKVN   6144
#define ATTN   2048

// Scratch (static device globals per harness rules)
static __device__ __nv_bfloat16 g_QKV[(size_t)TOK * QKVN]; // GEMM1 out (bf16, attn input)
static __device__ __half        g_ATT[(size_t)TOK * ATTN]; // attn out (f16, GEMM2 A)
static __device__ __half        g_X16[(size_t)TOK * DMODEL];  // x f16
static __device__ __half        g_W16[(size_t)QKVN * DMODEL]; // [Wq;Wk;Wv;Wqm;Wkm;Wvm] f16
static __device__ __half        g_WO16[(size_t)DMODEL * ATTN];// row n: [Wo[n,:]|Wom[n,:]] f16

struct Ptr6 { const float* p[6]; };

// ---------------------------------------------------------------------------
// helpers
// ---------------------------------------------------------------------------
__device__ __forceinline__ unsigned pack_bf2(float lo, float hi) {
  unsigned d;
  asm("cvt.rn.bf16x2.f32 %0, %1, %2;" : "=r"(d) : "f"(hi), "f"(lo));
  return d;
}
__device__ __forceinline__ unsigned pack_h2(float lo, float hi) {
  __half2 h = __floats2half2_rn(lo, hi);
  return *(unsigned*)&h;
}
__device__ __forceinline__ unsigned smem_u32(const void* p) {
  return (unsigned)__cvta_generic_to_shared(p);
}
__device__ __forceinline__ void ldm_x4(unsigned* r, unsigned addr) {
  asm volatile("ldmatrix.sync.aligned.m8n8.x4.shared.b16 {%0,%1,%2,%3}, [%4];"
               : "=r"(r[0]), "=r"(r[1]), "=r"(r[2]), "=r"(r[3]) : "r"(addr));
}
__device__ __forceinline__ void ldm_x4t(unsigned* r, unsigned addr) {
  asm volatile("ldmatrix.sync.aligned.m8n8.x4.trans.shared.b16 {%0,%1,%2,%3}, [%4];"
               : "=r"(r[0]), "=r"(r[1]), "=r"(r[2]), "=r"(r[3]) : "r"(addr));
}
// bf16 x bf16 -> f32 acc (attention)
__device__ __forceinline__ void mma_bf16(float* d, const unsigned* a,
                                         const unsigned* b, const float* c) {
  asm volatile(
      "mma.sync.aligned.m16n8k16.row.col.f32.bf16.bf16.f32 "
      "{%0,%1,%2,%3}, {%4,%5,%6,%7}, {%8,%9}, {%10,%11,%12,%13};"
      : "=f"(d[0]), "=f"(d[1]), "=f"(d[2]), "=f"(d[3])
      : "r"(a[0]), "r"(a[1]), "r"(a[2]), "r"(a[3]), "r"(b[0]), "r"(b[1]),
        "f"(c[0]), "f"(c[1]), "f"(c[2]), "f"(c[3]));
}
// f16 x f16 -> f16 acc (GEMMs; potentially 2x rate)
__device__ __forceinline__ void mma_f16(unsigned* d, const unsigned* a,
                                        const unsigned* b, const unsigned* c) {
  asm volatile(
      "mma.sync.aligned.m16n8k16.row.col.f16.f16.f16.f16 "
      "{%0,%1}, {%2,%3,%4,%5}, {%6,%7}, {%8,%9};"
      : "=r"(d[0]), "=r"(d[1])
      : "r"(a[0]), "r"(a[1]), "r"(a[2]), "r"(a[3]), "r"(b[0]), "r"(b[1]),
        "r"(c[0]), "r"(c[1]));
}
__device__ __forceinline__ void cpa16(unsigned dst, const void* src) {
  asm volatile("cp.async.cg.shared.global [%0], [%1], 16;" :: "r"(dst), "l"(src)
               : "memory");
}

// ---------------------------------------------------------------------------
// Conversion kernels (f32 -> f16 scratch)
// ---------------------------------------------------------------------------
__global__ void conv_x(const float4* __restrict__ src) {
  int i = blockIdx.x * 256 + threadIdx.x;            // over TOK*DMODEL/4
  float4 v = src[i];
  ((uint2*)g_X16)[i] = make_uint2(pack_h2(v.x, v.y), pack_h2(v.z, v.w));
}
__global__ void conv_w(Ptr6 W) {
  int i = blockIdx.x * 256 + threadIdx.x;            // over QKVN*DMODEL/4
  int row = i >> 8;                                   // 256 float4 per row
  const float4* src = (const float4*)W.p[row >> 10];
  float4 v = src[((row & 1023) << 8) + (i & 255)];
  ((uint2*)g_W16)[i] = make_uint2(pack_h2(v.x, v.y), pack_h2(v.z, v.w));
}
__global__ void conv_wo(const float4* __restrict__ Wo, const float4* __restrict__ Wom) {
  int i = blockIdx.x * 256 + threadIdx.x;            // over DMODEL*DMODEL/4
  int row = i >> 8, c = i & 255;
  float4 a = Wo[i], b = Wom[i];
  uint2* dst = (uint2*)g_WO16;
  dst[row * 512 + c]       = make_uint2(pack_h2(a.x, a.y), pack_h2(a.z, a.w));
  dst[row * 512 + 256 + c] = make_uint2(pack_h2(b.x, b.y), pack_h2(b.z, b.w));
}

// ---------------------------------------------------------------------------
// GEMM (f16 mma.sync with f16 accumulators, multistage):
// CTA tile 128(M) x 256(N), BK=32, 4 stages, 256 threads (8 warps, 64x64
// warp tile, 2M x 4N). f16 accs promoted to f32 regs every 4 chunks (K=128).
// MODE 0: A=g_X16 (K=1024)  B=g_W16  -> bf16 g_QKV
// MODE 1: A=g_ATT (K=2048)  B=g_WO16 -> f32 Out = acc + bo + bom + X
// ---------------------------------------------------------------------------
#define BPITCH  40
#define STAGES  4
#define STG_ELM ((128 + 256) * BPITCH)            // f16 per stage = 15360
#define GSMEM   (STAGES * STG_ELM * 2)            // 122880 B

template <int K, int MODE>
__global__ __launch_bounds__(256) void gemm_mma(
    const float* __restrict__ bo, const float* __restrict__ bom,
    const float* __restrict__ X, float* __restrict__ Out) {
  extern __shared__ __align__(16) __half sm[];
  const int tid = threadIdx.x;
  const int m0 = blockIdx.y * 128, n0 = blockIdx.x * 256;
  const __half* __restrict__ A = (MODE == 0) ? g_X16 : g_ATT;
  const __half* __restrict__ Bm = (MODE == 0) ? g_W16 : g_WO16;
  const int lane = tid & 31, wid = tid >> 5;
  const int wm = (wid & 1) * 64, wn = (wid >> 1) * 64;
  const int g = lane >> 2, tg = lane & 3;

  // per-stage loader: A 128x32 (512 x16B) then B 256x32 (1024 x16B); 6/thread
  auto load_stage = [&](int k0, int s) {
    __half* stg = sm + s * STG_ELM;
#pragma unroll
    for (int j = 0; j < 6; j++) {
      const int idx = tid + j * 256;
      if (idx < 512) {
        const int row = idx >> 2, c = (idx & 3) * 8;
        cpa16(smem_u32(&stg[row * BPITCH + c]),
              &A[(size_t)(m0 + row) * K + k0 + c]);
      } else {
        const int bidx = idx - 512;
        const int row = bidx >> 2, c = (bidx & 3) * 8;
        cpa16(smem_u32(&stg[128 * BPITCH + row * BPITCH + c]),
              &Bm[(size_t)(n0 + row) * K + k0 + c]);
      }
    }
  };

  float accf[4][8][4];
  unsigned acc16[4][8][2];
#pragma unroll
  for (int mi = 0; mi < 4; mi++)
#pragma unroll
    for (int ni = 0; ni < 8; ni++) {
#pragma unroll
      for (int r = 0; r < 4; r++) accf[mi][ni][r] = 0.f;
      acc16[mi][ni][0] = 0u; acc16[mi][ni][1] = 0u;
    }

  constexpr int NC = K / 32;   // 32 or 64; divisible by 4
  // prologue: 3 stages in flight
#pragma unroll
  for (int s = 0; s < STAGES - 1; s++) {
    load_stage(s * 32, s);
    asm volatile("cp.async.commit_group;" ::: "memory");
  }

#pragma unroll 1
  for (int kc = 0; kc < NC; kc++) {
    asm volatile("cp.async.wait_group %0;" :: "n"(STAGES - 2) : "memory");
    __syncthreads();
    if (kc + STAGES - 1 < NC)
      load_stage((kc + STAGES - 1) * 32, (kc + STAGES - 1) % STAGES);
    asm volatile("cp.async.commit_group;" ::: "memory");

    const int s = kc % STAGES;
    const unsigned as = smem_u32(sm + s * STG_ELM);
    const unsigned bs = as + 128 * BPITCH * 2;
#pragma unroll
    for (int ks = 0; ks < 2; ks++) {
      const int kk = ks * 16;
      unsigned afr[4][4];
#pragma unroll
      for (int mi = 0; mi < 4; mi++)
        ldm_x4(afr[mi],
               as + ((wm + mi * 16 + (lane & 15)) * BPITCH + kk + (lane >> 4) * 8) * 2);
#pragma unroll
      for (int n2 = 0; n2 < 4; n2++) {
        unsigned bfr[4];
        ldm_x4(bfr, bs + ((wn + n2 * 16 + (lane >> 4) * 8 + (lane & 7)) * BPITCH +
                          kk + ((lane >> 3) & 1) * 8) * 2);
#pragma unroll
        for (int mi = 0; mi < 4; mi++) {
          mma_f16(acc16[mi][2 * n2], afr[mi], bfr, acc16[mi][2 * n2]);
          mma_f16(acc16[mi][2 * n2 + 1], afr[mi], bfr + 2, acc16[mi][2 * n2 + 1]);
        }
      }
    }
    // promote f16 accumulators to f32 every 4 chunks (K=128 slice)
    if ((kc & 3) == 3) {
#pragma unroll
      for (int mi = 0; mi < 4; mi++)
#pragma unroll
        for (int ni = 0; ni < 8; ni++) {
          float2 f0 = __half22float2(*(__half2*)&acc16[mi][ni][0]);
          float2 f1 = __half22float2(*(__half2*)&acc16[mi][ni][1]);
          accf[mi][ni][0] += f0.x; accf[mi][ni][1] += f0.y;
          accf[mi][ni][2] += f1.x; accf[mi][ni][3] += f1.y;
          acc16[mi][ni][0] = 0u; acc16[mi][ni][1] = 0u;
        }
    }
  }

#pragma unroll
  for (int mi = 0; mi < 4; mi++)
#pragma unroll
    for (int ni = 0; ni < 8; ni++) {
      const int row = m0 + wm + mi * 16 + g;
      const int col = n0 + wn + ni * 8 + 2 * tg;
      if (MODE == 0) {
        *(unsigned*)&g_QKV[(size_t)row * QKVN + col] =
            pack_bf2(accf[mi][ni][0], accf[mi][ni][1]);
        *(unsigned*)&g_QKV[(size_t)(row + 8) * QKVN + col] =
            pack_bf2(accf[mi][ni][2], accf[mi][ni][3]);
      } else {
        const float bias0 = bo[col] + bom[col];
        const float bias1 = bo[col + 1] + bom[col + 1];
        float2 x0 = *(const float2*)&X[(size_t)row * DMODEL + col];
        float2 x1 = *(const float2*)&X[(size_t)(row + 8) * DMODEL + col];
        *(float2*)&Out[(size_t)row * DMODEL + col] =
            make_float2(accf[mi][ni][0] + bias0 + x0.x, accf[mi][ni][1] + bias1 + x0.y);
        *(float2*)&Out[(size_t)(row + 8) * DMODEL + col] =
            make_float2(accf[mi][ni][2] + bias0 + x1.x, accf[mi][ni][3] + bias1 + x1.y);
      }
    }
}

// ---------------------------------------------------------------------------
// Flash attention (bf16 mma.sync, f32 softmax) — math identical to R3..R9;
// only the g_ATT output packing changed to f16.
// ---------------------------------------------------------------------------
#define APITCH 72

__device__ __forceinline__ void fa_tile(
    unsigned qsm, unsigned ksm, unsigned vsm, int lane, int wrow,
    float& m0v, float& m1v, float& l0, float& l1, float o[8][4]) {
  const int half = (lane >> 3) & 1, quad = lane >> 4;
  float s[8][4];
#pragma unroll
  for (int nf = 0; nf < 8; nf++)
#pragma unroll
    for (int r = 0; r < 4; r++) s[nf][r] = 0.f;
#pragma unroll
  for (int kcc = 0; kcc < 4; kcc++) {
    unsigned a[4];
    ldm_x4(a, qsm + ((wrow + (lane & 15)) * APITCH + kcc * 16 + quad * 8) * 2);
#pragma unroll
    for (int n2 = 0; n2 < 4; n2++) {
      unsigned bf[4];
      ldm_x4(bf, ksm + ((n2 * 16 + quad * 8 + (lane & 7)) * APITCH + kcc * 16 + half * 8) * 2);
      mma_bf16(s[2 * n2], a, bf, s[2 * n2]);
      mma_bf16(s[2 * n2 + 1], a, bf + 2, s[2 * n2 + 1]);
    }
  }
  float mx0 = -1e30f, mx1 = -1e30f;
#pragma unroll
  for (int nf = 0; nf < 8; nf++) {
#pragma unroll
    for (int r = 0; r < 4; r++) s[nf][r] *= 0.125f;
    mx0 = fmaxf(mx0, fmaxf(s[nf][0], s[nf][1]));
    mx1 = fmaxf(mx1, fmaxf(s[nf][2], s[nf][3]));
  }
  mx0 = fmaxf(mx0, __shfl_xor_sync(0xffffffffu, mx0, 1));
  mx0 = fmaxf(mx0, __shfl_xor_sync(0xffffffffu, mx0, 2));
  mx1 = fmaxf(mx1, __shfl_xor_sync(0xffffffffu, mx1, 1));
  mx1 = fmaxf(mx1, __shfl_xor_sync(0xffffffffu, mx1, 2));
  const float nm0 = fmaxf(m0v, mx0), nm1 = fmaxf(m1v, mx1);
  const float c0 = __expf(m0v - nm0), c1 = __expf(m1v - nm1);
  m0v = nm0; m1v = nm1;
  float sum0 = 0.f, sum1 = 0.f;
  unsigned pa[4][4];
#pragma unroll
  for (int j = 0; j < 4; j++) {
    float p00 = __expf(s[2 * j][0] - nm0), p01 = __expf(s[2 * j][1] - nm0);
    float p02 = __expf(s[2 * j][2] - nm1), p03 = __expf(s[2 * j][3] - nm1);
    float p10 = __expf(s[2 * j + 1][0] - nm0), p11 = __expf(s[2 * j + 1][1] - nm0);
    float p12 = __expf(s[2 * j + 1][2] - nm1), p13 = __expf(s[2 * j + 1][3] - nm1);
    pa[j][0] = pack_bf2(p00, p01);
    pa[j][1] = pack_bf2(p02, p03);
    pa[j][2] = pack_bf2(p10, p11);
    pa[j][3] = pack_bf2(p12, p13);
    sum0 += p00 + p01 + p10 + p11;
    sum1 += p02 + p03 + p12 + p13;
  }
  sum0 += __shfl_xor_sync(0xffffffffu, sum0, 1);
  sum0 += __shfl_xor_sync(0xffffffffu, sum0, 2);
  sum1 += __shfl_xor_sync(0xffffffffu, sum1, 1);
  sum1 += __shfl_xor_sync(0xffffffffu, sum1, 2);
  l0 = l0 * c0 + sum0;
  l1 = l1 * c1 + sum1;
#pragma unroll
  for (int df = 0; df < 8; df++) {
    o[df][0] *= c0; o[df][1] *= c0; o[df][2] *= c1; o[df][3] *= c1;
  }
#pragma unroll
  for (int j = 0; j < 4; j++)
#pragma unroll
    for (int d2 = 0; d2 < 4; d2++) {
      unsigned bf[4];
      ldm_x4t(bf, vsm + ((j * 16 + half * 8 + (lane & 7)) * APITCH + d2 * 16 + quad * 8) * 2);
      mma_bf16(o[2 * d2], pa[j], bf, o[2 * d2]);
      mma_bf16(o[2 * d2 + 1], pa[j], bf + 2, o[2 * d2 + 1]);
    }
}

__global__ __launch_bounds__(128) void attn_main() {
  __shared__ __align__(16) __nv_bfloat16 Qs[64 * APITCH];
  __shared__ __align__(16) __nv_bfloat16 Ks[64 * APITCH];
  __shared__ __align__(16) __nv_bfloat16 Vs[64 * APITCH];
  const int tid = threadIdx.x, lane = tid & 31, w = tid >> 5;
  const int qt = blockIdx.x;
  const int b = blockIdx.y >> 4, h = blockIdx.y & 15;
  const int tb = b << 10;
  const int colQ = h * 64, colK = 1024 + h * 64, colV = 2048 + h * 64;

#pragma unroll
  for (int i = 0; i < 4; i++) {
    int u = tid + i * 128;
    int r = u >> 3, o8 = (u & 7) * 8;
    *(uint4*)&Qs[r * APITCH + o8] =
        *(const uint4*)&g_QKV[(size_t)(tb + qt * 64 + r) * QKVN + colQ + o8];
  }
  const int g = lane >> 2, tg = lane & 3;
  const int wrow = w * 16;
  float m0v = -1e30f, m1v = -1e30f, l0 = 0.f, l1 = 0.f;
  float o[8][4];
#pragma unroll
  for (int df = 0; df < 8; df++)
#pragma unroll
    for (int r = 0; r < 4; r++) o[df][r] = 0.f;
  const unsigned qsm = smem_u32(Qs), ksm = smem_u32(Ks), vsm = smem_u32(Vs);

  for (int kt = 0; kt < 16; kt++) {
    __syncthreads();
#pragma unroll
    for (int i = 0; i < 4; i++) {
      int u = tid + i * 128;
      int r = u >> 3, o8 = (u & 7) * 8;
      size_t trow = (size_t)(tb + kt * 64 + r) * QKVN;
      *(uint4*)&Ks[r * APITCH + o8] = *(const uint4*)&g_QKV[trow + colK + o8];
      *(uint4*)&Vs[r * APITCH + o8] = *(const uint4*)&g_QKV[trow + colV + o8];
    }
    __syncthreads();
    fa_tile(qsm, ksm, vsm, lane, wrow, m0v, m1v, l0, l1, o);
  }
  const float i0 = 1.f / l0, i1 = 1.f / l1;
  const int row = tb + qt * 64 + wrow + g;
#pragma unroll
  for (int df = 0; df < 8; df++) {
    const int col = h * 64 + df * 8 + 2 * tg;
    *(unsigned*)&g_ATT[(size_t)row * ATTN + col] = pack_h2(o[df][0] * i0, o[df][1] * i0);
    *(unsigned*)&g_ATT[(size_t)(row + 8) * ATTN + col] = pack_h2(o[df][2] * i1, o[df][3] * i1);
  }
}

__device__ __forceinline__ int mv_token(int bb, int j, int ij, int is_col) {
  int c = j >> 5, pos = j & 31;
  int nv = is_col ? ((c < 3) ? 2 * c : 5) : c;  // COL_IDX = {0,2,4,5}
  int s  = is_col ? (pos * 32 + ij) : (ij * 32 + pos);
  return (bb * 6 + nv) * 1024 + s;
}

template <int IS_COL>
__global__ __launch_bounds__(128) void attn_mv() {
  __shared__ __align__(16) __nv_bfloat16 Qs[64 * APITCH];
  __shared__ __align__(16) __nv_bfloat16 Ks[64 * APITCH];
  __shared__ __align__(16) __nv_bfloat16 Vs[64 * APITCH];
  const int tid = threadIdx.x, lane = tid & 31, w = tid >> 5;
  const int qt = blockIdx.x;                // 0..1
  const int gy = blockIdx.y;
  const int h = gy & 15;
  const int ij = (gy >> 4) & 31;
  const int bb = gy >> 9;
  const int colQ = 3072 + h * 64, colK = 4096 + h * 64, colV = 5120 + h * 64;

#pragma unroll
  for (int i = 0; i < 4; i++) {
    int u = tid + i * 128;
    int r = u >> 3, o8 = (u & 7) * 8;
    int t = mv_token(bb, qt * 64 + r, ij, IS_COL);
    *(uint4*)&Qs[r * APITCH + o8] = *(const uint4*)&g_QKV[(size_t)t * QKVN + colQ + o8];
  }
  const int g = lane >> 2, tg = lane & 3;
  const int wrow = w * 16;
  float m0v = -1e30f, m1v = -1e30f, l0 = 0.f, l1 = 0.f;
  float o[8][4];
#pragma unroll
  for (int df = 0; df < 8; df++)
#pragma unroll
    for (int r = 0; r < 4; r++) o[df][r] = 0.f;
  const unsigned qsm = smem_u32(Qs), ksm = smem_u32(Ks), vsm = smem_u32(Vs);

  for (int kt = 0; kt < 2; kt++) {
    __syncthreads();
#pragma unroll
    for (int i = 0; i < 4; i++) {
      int u = tid + i * 128;
      int r = u >> 3, o8 = (u & 7) * 8;
      size_t trow = (size_t)mv_token(bb, kt * 64 + r, ij, IS_COL) * QKVN;
      *(uint4*)&Ks[r * APITCH + o8] = *(const uint4*)&g_QKV[trow + colK + o8];
      *(uint4*)&Vs[r * APITCH + o8] = *(const uint4*)&g_QKV[trow + colV + o8];
    }
    __syncthreads();
    fa_tile(qsm, ksm, vsm, lane, wrow, m0v, m1v, l0, l1, o);
  }
  const float i0 = 1.f / l0, i1 = 1.f / l1;
  const int t0 = mv_token(bb, qt * 64 + wrow + g, ij, IS_COL);
  const int t1 = mv_token(bb, qt * 64 + wrow + g + 8, ij, IS_COL);
  const int half16 = w >> 1;
#pragma unroll
  for (int df = 0; df < 8; df++) {
    const int col = 1024 + h * 64 + df * 8 + 2 * tg;
    float v00 = o[df][0] * i0, v01 = o[df][1] * i0;
    float v10 = o[df][2] * i1, v11 = o[df][3] * i1;
    unsigned* d0 = (unsigned*)&g_ATT[(size_t)t0 * ATTN + col];
    unsigned* d1 = (unsigned*)&g_ATT[(size_t)t1 * ATTN + col];
    if (IS_COL) {
      const float wgt = (qt == 0) ? 0.5f : 1.0f;
      *d0 = pack_h2(v00 * wgt, v01 * wgt);
      *d1 = pack_h2(v10 * wgt, v11 * wgt);
    } else {
      if (half16 == 0) {
        float2 p0 = __half22float2(*(__half2*)d0);
        float2 p1 = __half22float2(*(__half2*)d1);
        *d0 = pack_h2(p0.x + 0.5f * v00, p0.y + 0.5f * v01);
        *d1 = pack_h2(p1.x + 0.5f * v10, p1.y + 0.5f * v11);
      } else {
        *d0 = pack_h2(v00, v01);
        *d1 = pack_h2(v10, v11);
      }
    }
  }
}

// ---------------------------------------------------------------------------
extern "C" void kernel_launch(void* const* d_in, const int* in_sizes, int n_in,
                              void* d_out, int out_size) {
  (void)in_sizes; (void)n_in; (void)out_size;
  const float* x   = (const float*)d_in[0];
  const float* Wq  = (const float*)d_in[1];
  const float* Wk  = (const float*)d_in[2];
  const float* Wv  = (const float*)d_in[3];
  const float* Wo  = (const float*)d_in[4];
  const float* bo  = (const float*)d_in[5];
  const float* Wqm = (const float*)d_in[6];
  const float* Wkm = (const float*)d_in[7];
  const float* Wvm = (const float*)d_in[8];
  const float* Wom = (const float*)d_in[9];
  const float* bom = (const float*)d_in[10];
  float* out = (float*)d_out;

  cudaFuncSetAttribute(gemm_mma<DMODEL, 0>,
                       cudaFuncAttributeMaxDynamicSharedMemorySize, GSMEM);
  cudaFuncSetAttribute(gemm_mma<ATTN, 1>,
                       cudaFuncAttributeMaxDynamicSharedMemorySize, GSMEM);

  Ptr6 W6;
  W6.p[0] = Wq;  W6.p[1] = Wk;  W6.p[2] = Wv;
  W6.p[3] = Wqm; W6.p[4] = Wkm; W6.p[5] = Wvm;

  conv_x<<<TOK * DMODEL / 1024, 256>>>((const float4*)x);
  conv_w<<<QKVN * DMODEL / 1024, 256>>>(W6);
  conv_wo<<<DMODEL * DMODEL / 1024, 256>>>((const float4*)Wo, (const float4*)Wom);

  gemm_mma<DMODEL, 0><<<dim3(QKVN / 256, TOK / 128), 256, GSMEM>>>(
      nullptr, nullptr, nullptr, nullptr);
  attn_main<<<dim3(16, 192), 128>>>();
  attn_mv<1><<<dim3(2, 1024), 128>>>();
  attn_mv<0><<<dim3(2, 1024), 128>>>();
  gemm_mma<ATTN, 1><<<dim3(DMODEL / 256, TOK / 128), 256, GSMEM>>>(
      bo, bom, x, out);
}

// round 11
// speedup vs baseline: 1.0691x; 1.0691x over previous
#include <cuda_runtime.h>
#include <cuda_bf16.h>
#include <cstdint>
#include <cstddef>

#define TOK    12288
#define DMODEL 1024
#define QKVN   6144
#define ATTN   2048

// Scratch (static device globals per harness rules)
static __device__ __nv_bfloat16 g_QKV[(size_t)TOK * QKVN];    // GEMM1 out
static __device__ __nv_bfloat16 g_ATT[(size_t)TOK * ATTN];    // attn out (GEMM2 A)
static __device__ __nv_bfloat16 g_X16[(size_t)TOK * DMODEL];  // x bf16
static __device__ __nv_bfloat16 g_W16[(size_t)QKVN * DMODEL]; // [Wq;Wk;Wv;Wqm;Wkm;Wvm]
static __device__ __nv_bfloat16 g_WO16[(size_t)DMODEL * ATTN];// row n: [Wo[n,:]|Wom[n,:]]

struct Ptr6 { const float* p[6]; };

// ---------------------------------------------------------------------------
// helpers
// ---------------------------------------------------------------------------
__device__ __forceinline__ unsigned pack_bf2(float lo, float hi) {
  unsigned d;
  asm("cvt.rn.bf16x2.f32 %0, %1, %2;" : "=r"(d) : "f"(hi), "f"(lo));
  return d;
}
__device__ __forceinline__ unsigned smem_u32(const void* p) {
  return (unsigned)__cvta_generic_to_shared(p);
}
__device__ __forceinline__ void ldm_x4(unsigned* r, unsigned addr) {
  asm volatile("ldmatrix.sync.aligned.m8n8.x4.shared.b16 {%0,%1,%2,%3}, [%4];"
               : "=r"(r[0]), "=r"(r[1]), "=r"(r[2]), "=r"(r[3]) : "r"(addr));
}
__device__ __forceinline__ void ldm_x4t(unsigned* r, unsigned addr) {
  asm volatile("ldmatrix.sync.aligned.m8n8.x4.trans.shared.b16 {%0,%1,%2,%3}, [%4];"
               : "=r"(r[0]), "=r"(r[1]), "=r"(r[2]), "=r"(r[3]) : "r"(addr));
}
__device__ __forceinline__ void mma_bf16(float* d, const unsigned* a,
                                         const unsigned* b, const float* c) {
  asm volatile(
      "mma.sync.aligned.m16n8k16.row.col.f32.bf16.bf16.f32 "
      "{%0,%1,%2,%3}, {%4,%5,%6,%7}, {%8,%9}, {%10,%11,%12,%13};"
      : "=f"(d[0]), "=f"(d[1]), "=f"(d[2]), "=f"(d[3])
      : "r"(a[0]), "r"(a[1]), "r"(a[2]), "r"(a[3]), "r"(b[0]), "r"(b[1]),
        "f"(c[0]), "f"(c[1]), "f"(c[2]), "f"(c[3]));
}
__device__ __forceinline__ void cpa16(unsigned dst, const void* src) {
  asm volatile("cp.async.cg.shared.global [%0], [%1], 16;" :: "r"(dst), "l"(src)
               : "memory");
}

// ---------------------------------------------------------------------------
// Fused prep kernel: f32->bf16 conversions + zero-init of g_ATT mv half.
// Job ranges (in 16B/float4 units):
//   [0, NX)            : x -> g_X16
//   [NX, NX+NW)        : 6 QKV weights -> g_W16
//   [NX+NW, +NWO)      : Wo|Wom -> g_WO16
//   [.., +NZ)          : zero g_ATT[:, 1024:2048]
// ---------------------------------------------------------------------------
#define NX  (TOK * DMODEL / 4)          // 3145728
#define NW  (QKVN * DMODEL / 4)         // 6291456
#define NWO (DMODEL * DMODEL / 4)       // 262144
#define NZ  (TOK * 1024 / 8)            // 1572864 (uint4 over bf16)
#define NALL (NX + NW + NWO + NZ)       // 11272192 -> 44032 blocks of 256

__global__ void prep_all(const float4* __restrict__ x, Ptr6 W,
                         const float4* __restrict__ Wo,
                         const float4* __restrict__ Wom) {
  int i = blockIdx.x * 256 + threadIdx.x;
  if (i < NX) {
    float4 v = x[i];
    ((uint2*)g_X16)[i] = make_uint2(pack_bf2(v.x, v.y), pack_bf2(v.z, v.w));
  } else if (i < NX + NW) {
    int j = i - NX;
    int row = j >> 8;                                 // 256 float4 per row
    const float4* src = (const float4*)W.p[row >> 10];
    float4 v = src[((row & 1023) << 8) + (j & 255)];
    ((uint2*)g_W16)[j] = make_uint2(pack_bf2(v.x, v.y), pack_bf2(v.z, v.w));
  } else if (i < NX + NW + NWO) {
    int j = i - NX - NW;
    int row = j >> 8, c = j & 255;
    float4 a = Wo[j], b = Wom[j];
    uint2* dst = (uint2*)g_WO16;
    dst[row * 512 + c]       = make_uint2(pack_bf2(a.x, a.y), pack_bf2(a.z, a.w));
    dst[row * 512 + 256 + c] = make_uint2(pack_bf2(b.x, b.y), pack_bf2(b.z, b.w));
  } else {
    int j = i - NX - NW - NWO;
    int row = j >> 7, c = (j & 127) * 8;
    *(uint4*)&g_ATT[(size_t)row * ATTN + 1024 + c] = make_uint4(0, 0, 0, 0);
  }
}

// ---------------------------------------------------------------------------
// GEMM (bf16 mma.sync, multistage) — byte-identical to Round 7 (best).
// CTA tile 128x256, BK=32, 4 stages, 256 threads (8 warps, 64x64 warp tile).
// MODE 0: A=g_X16 (K=1024)  B=g_W16  -> bf16 g_QKV
// MODE 1: A=g_ATT (K=2048)  B=g_WO16 -> f32 Out = acc + bo + bom + X
// ---------------------------------------------------------------------------
#define BPITCH  40
#define STAGES  4
#define STG_ELM ((128 + 256) * BPITCH)            // bf16 per stage = 15360
#define GSMEM   (STAGES * STG_ELM * 2)            // 122880 B

template <int K, int MODE>
__global__ __launch_bounds__(256) void gemm_mma(
    const float* __restrict__ bo, const float* __restrict__ bom,
    const float* __restrict__ X, float* __restrict__ Out) {
  extern __shared__ __align__(16) __nv_bfloat16 sm[];
  const int tid = threadIdx.x;
  const int m0 = blockIdx.y * 128, n0 = blockIdx.x * 256;
  const __nv_bfloat16* __restrict__ A = (MODE == 0) ? g_X16 : g_ATT;
  const __nv_bfloat16* __restrict__ Bm = (MODE == 0) ? g_W16 : g_WO16;
  const int lane = tid & 31, wid = tid >> 5;
  const int wm = (wid & 1) * 64, wn = (wid >> 1) * 64;
  const int g = lane >> 2, tg = lane & 3;

  auto load_stage = [&](int k0, int s) {
    __nv_bfloat16* stg = sm + s * STG_ELM;
#pragma unroll
    for (int j = 0; j < 6; j++) {
      const int idx = tid + j * 256;
      if (idx < 512) {
        const int row = idx >> 2, c = (idx & 3) * 8;
        cpa16(smem_u32(&stg[row * BPITCH + c]),
              &A[(size_t)(m0 + row) * K + k0 + c]);
      } else {
        const int bidx = idx - 512;
        const int row = bidx >> 2, c = (bidx & 3) * 8;
        cpa16(smem_u32(&stg[128 * BPITCH + row * BPITCH + c]),
              &Bm[(size_t)(n0 + row) * K + k0 + c]);
      }
    }
  };

  float acc[4][8][4];
#pragma unroll
  for (int mi = 0; mi < 4; mi++)
#pragma unroll
    for (int ni = 0; ni < 8; ni++)
#pragma unroll
      for (int r = 0; r < 4; r++) acc[mi][ni][r] = 0.f;

  constexpr int NC = K / 32;
#pragma unroll
  for (int s = 0; s < STAGES - 1; s++) {
    load_stage(s * 32, s);
    asm volatile("cp.async.commit_group;" ::: "memory");
  }

#pragma unroll 1
  for (int kc = 0; kc < NC; kc++) {
    asm volatile("cp.async.wait_group %0;" :: "n"(STAGES - 2) : "memory");
    __syncthreads();
    if (kc + STAGES - 1 < NC)
      load_stage((kc + STAGES - 1) * 32, (kc + STAGES - 1) % STAGES);
    asm volatile("cp.async.commit_group;" ::: "memory");

    const int s = kc % STAGES;
    const unsigned as = smem_u32(sm + s * STG_ELM);
    const unsigned bs = as + 128 * BPITCH * 2;
#pragma unroll
    for (int ks = 0; ks < 2; ks++) {
      const int kk = ks * 16;
      unsigned afr[4][4];
#pragma unroll
      for (int mi = 0; mi < 4; mi++)
        ldm_x4(afr[mi],
               as + ((wm + mi * 16 + (lane & 15)) * BPITCH + kk + (lane >> 4) * 8) * 2);
#pragma unroll
      for (int n2 = 0; n2 < 4; n2++) {
        unsigned bfr[4];
        ldm_x4(bfr, bs + ((wn + n2 * 16 + (lane >> 4) * 8 + (lane & 7)) * BPITCH +
                          kk + ((lane >> 3) & 1) * 8) * 2);
#pragma unroll
        for (int mi = 0; mi < 4; mi++) {
          mma_bf16(acc[mi][2 * n2], afr[mi], bfr, acc[mi][2 * n2]);
          mma_bf16(acc[mi][2 * n2 + 1], afr[mi], bfr + 2, acc[mi][2 * n2 + 1]);
        }
      }
    }
  }

#pragma unroll
  for (int mi = 0; mi < 4; mi++)
#pragma unroll
    for (int ni = 0; ni < 8; ni++) {
      const int row = m0 + wm + mi * 16 + g;
      const int col = n0 + wn + ni * 8 + 2 * tg;
      if (MODE == 0) {
        *(unsigned*)&g_QKV[(size_t)row * QKVN + col] =
            pack_bf2(acc[mi][ni][0], acc[mi][ni][1]);
        *(unsigned*)&g_QKV[(size_t)(row + 8) * QKVN + col] =
            pack_bf2(acc[mi][ni][2], acc[mi][ni][3]);
      } else {
        const float bias0 = bo[col] + bom[col];
        const float bias1 = bo[col + 1] + bom[col + 1];
        float2 x0 = *(const float2*)&X[(size_t)row * DMODEL + col];
        float2 x1 = *(const float2*)&X[(size_t)(row + 8) * DMODEL + col];
        *(float2*)&Out[(size_t)row * DMODEL + col] =
            make_float2(acc[mi][ni][0] + bias0 + x0.x, acc[mi][ni][1] + bias1 + x0.y);
        *(float2*)&Out[(size_t)(row + 8) * DMODEL + col] =
            make_float2(acc[mi][ni][2] + bias0 + x1.x, acc[mi][ni][3] + bias1 + x1.y);
      }
    }
}

// ---------------------------------------------------------------------------
// Fused flash attention: main + col views + row views in ONE launch.
//   blockIdx.x in [0, 3072)      : main   (qt = bx & 15, bh = bx >> 4)
//   blockIdx.x in [3072, 5120)   : col    (u = bx-3072: qt = u & 1, gy = u >> 1)
//   blockIdx.x in [5120, 7168)   : row    (u = bx-5120: qt = u & 1, gy = u >> 1)
// mv epilogues atomicAdd weighted results into the zeroed g_ATT mv half
// (<=2 commutative contributors per location -> deterministic).
// ---------------------------------------------------------------------------
#define APITCH 72

__device__ __forceinline__ int mv_token(int bb, int j, int ij, int is_col) {
  int c = j >> 5, pos = j & 31;
  int nv = is_col ? ((c < 3) ? 2 * c : 5) : c;  // COL_IDX = {0,2,4,5}
  int s  = is_col ? (pos * 32 + ij) : (ij * 32 + pos);
  return (bb * 6 + nv) * 1024 + s;
}

__device__ __forceinline__ void fa_tile(
    unsigned qsm, unsigned ksm, unsigned vsm, int lane, int wrow,
    float& m0v, float& m1v, float& l0, float& l1, float o[8][4]) {
  const int half = (lane >> 3) & 1, quad = lane >> 4;
  float s[8][4];
#pragma unroll
  for (int nf = 0; nf < 8; nf++)
#pragma unroll
    for (int r = 0; r < 4; r++) s[nf][r] = 0.f;
#pragma unroll
  for (int kcc = 0; kcc < 4; kcc++) {
    unsigned a[4];
    ldm_x4(a, qsm + ((wrow + (lane & 15)) * APITCH + kcc * 16 + quad * 8) * 2);
#pragma unroll
    for (int n2 = 0; n2 < 4; n2++) {
      unsigned bf[4];
      ldm_x4(bf, ksm + ((n2 * 16 + quad * 8 + (lane & 7)) * APITCH + kcc * 16 + half * 8) * 2);
      mma_bf16(s[2 * n2], a, bf, s[2 * n2]);
      mma_bf16(s[2 * n2 + 1], a, bf + 2, s[2 * n2 + 1]);
    }
  }
  float mx0 = -1e30f, mx1 = -1e30f;
#pragma unroll
  for (int nf = 0; nf < 8; nf++) {
#pragma unroll
    for (int r = 0; r < 4; r++) s[nf][r] *= 0.125f;
    mx0 = fmaxf(mx0, fmaxf(s[nf][0], s[nf][1]));
    mx1 = fmaxf(mx1, fmaxf(s[nf][2], s[nf][3]));
  }
  mx0 = fmaxf(mx0, __shfl_xor_sync(0xffffffffu, mx0, 1));
  mx0 = fmaxf(mx0, __shfl_xor_sync(0xffffffffu, mx0, 2));
  mx1 = fmaxf(mx1, __shfl_xor_sync(0xffffffffu, mx1, 1));
  mx1 = fmaxf(mx1, __shfl_xor_sync(0xffffffffu, mx1, 2));
  const float nm0 = fmaxf(m0v, mx0), nm1 = fmaxf(m1v, mx1);
  const float c0 = __expf(m0v - nm0), c1 = __expf(m1v - nm1);
  m0v = nm0; m1v = nm1;
  float sum0 = 0.f, sum1 = 0.f;
  unsigned pa[4][4];
#pragma unroll
  for (int j = 0; j < 4; j++) {
    float p00 = __expf(s[2 * j][0] - nm0), p01 = __expf(s[2 * j][1] - nm0);
    float p02 = __expf(s[2 * j][2] - nm1), p03 = __expf(s[2 * j][3] - nm1);
    float p10 = __expf(s[2 * j + 1][0] - nm0), p11 = __expf(s[2 * j + 1][1] - nm0);
    float p12 = __expf(s[2 * j + 1][2] - nm1), p13 = __expf(s[2 * j + 1][3] - nm1);
    pa[j][0] = pack_bf2(p00, p01);
    pa[j][1] = pack_bf2(p02, p03);
    pa[j][2] = pack_bf2(p10, p11);
    pa[j][3] = pack_bf2(p12, p13);
    sum0 += p00 + p01 + p10 + p11;
    sum1 += p02 + p03 + p12 + p13;
  }
  sum0 += __shfl_xor_sync(0xffffffffu, sum0, 1);
  sum0 += __shfl_xor_sync(0xffffffffu, sum0, 2);
  sum1 += __shfl_xor_sync(0xffffffffu, sum1, 1);
  sum1 += __shfl_xor_sync(0xffffffffu, sum1, 2);
  l0 = l0 * c0 + sum0;
  l1 = l1 * c1 + sum1;
#pragma unroll
  for (int df = 0; df < 8; df++) {
    o[df][0] *= c0; o[df][1] *= c0; o[df][2] *= c1; o[df][3] *= c1;
  }
#pragma unroll
  for (int j = 0; j < 4; j++)
#pragma unroll
    for (int d2 = 0; d2 < 4; d2++) {
      unsigned bf[4];
      ldm_x4t(bf, vsm + ((j * 16 + half * 8 + (lane & 7)) * APITCH + d2 * 16 + quad * 8) * 2);
      mma_bf16(o[2 * d2], pa[j], bf, o[2 * d2]);
      mma_bf16(o[2 * d2 + 1], pa[j], bf + 2, o[2 * d2 + 1]);
    }
}

__global__ __launch_bounds__(128) void attn_all() {
  __shared__ __align__(16) __nv_bfloat16 Qs[64 * APITCH];
  __shared__ __align__(16) __nv_bfloat16 Ks[64 * APITCH];
  __shared__ __align__(16) __nv_bfloat16 Vs[64 * APITCH];
  const int tid = threadIdx.x, lane = tid & 31, w = tid >> 5;
  const int bx = blockIdx.x;

  // role decode
  const int role = (bx < 3072) ? 0 : (bx < 5120) ? 1 : 2;  // 0=main 1=col 2=row
  int qt, h, bb, ij, tb = 0;
  if (role == 0) {
    qt = bx & 15;
    const int by = bx >> 4;
    h = by & 15;
    tb = (by >> 4) << 10;
    bb = 0; ij = 0;
  } else {
    const int u = bx - (role == 1 ? 3072 : 5120);
    qt = u & 1;
    const int gy = u >> 1;
    h = gy & 15;
    ij = (gy >> 4) & 31;
    bb = gy >> 9;
  }
  const int is_col = (role == 1);
  const int colQ = (role == 0 ? 0 : 3072) + h * 64;
  const int colK = colQ + 1024;
  const int colV = colQ + 2048;
  const int ktmax = (role == 0) ? 16 : 2;

  auto token = [&](int r) -> int {
    return (role == 0) ? (tb + qt * 64 + r) : mv_token(bb, qt * 64 + r, ij, is_col);
  };
  auto ktoken = [&](int kt, int r) -> int {
    return (role == 0) ? (tb + kt * 64 + r) : mv_token(bb, kt * 64 + r, ij, is_col);
  };

#pragma unroll
  for (int i = 0; i < 4; i++) {
    int u = tid + i * 128;
    int r = u >> 3, o8 = (u & 7) * 8;
    *(uint4*)&Qs[r * APITCH + o8] =
        *(const uint4*)&g_QKV[(size_t)token(r) * QKVN + colQ + o8];
  }
  const int g = lane >> 2, tg = lane & 3;
  const int wrow = w * 16;
  float m0v = -1e30f, m1v = -1e30f, l0 = 0.f, l1 = 0.f;
  float o[8][4];
#pragma unroll
  for (int df = 0; df < 8; df++)
#pragma unroll
    for (int r = 0; r < 4; r++) o[df][r] = 0.f;
  const unsigned qsm = smem_u32(Qs), ksm = smem_u32(Ks), vsm = smem_u32(Vs);

#pragma unroll 1
  for (int kt = 0; kt < ktmax; kt++) {
    __syncthreads();
#pragma unroll
    for (int i = 0; i < 4; i++) {
      int u = tid + i * 128;
      int r = u >> 3, o8 = (u & 7) * 8;
      size_t trow = (size_t)ktoken(kt, r) * QKVN;
      *(uint4*)&Ks[r * APITCH + o8] = *(const uint4*)&g_QKV[trow + colK + o8];
      *(uint4*)&Vs[r * APITCH + o8] = *(const uint4*)&g_QKV[trow + colV + o8];
    }
    __syncthreads();
    fa_tile(qsm, ksm, vsm, lane, wrow, m0v, m1v, l0, l1, o);
  }

  const float i0 = 1.f / l0, i1 = 1.f / l1;
  if (role == 0) {
    const int row = tb + qt * 64 + wrow + g;
#pragma unroll
    for (int df = 0; df < 8; df++) {
      const int col = h * 64 + df * 8 + 2 * tg;
      *(unsigned*)&g_ATT[(size_t)row * ATTN + col] =
          pack_bf2(o[df][0] * i0, o[df][1] * i0);
      *(unsigned*)&g_ATT[(size_t)(row + 8) * ATTN + col] =
          pack_bf2(o[df][2] * i1, o[df][3] * i1);
    }
  } else {
    const int t0 = mv_token(bb, qt * 64 + wrow + g, ij, is_col);
    const int t1 = mv_token(bb, qt * 64 + wrow + g + 8, ij, is_col);
    float wgt;
    if (is_col) {
      wgt = (qt == 0) ? 0.5f : 1.0f;            // c in {0,1} -> 0.5
    } else {
      const int nv = 2 * qt + (w >> 1);          // row view index 0..3
      wgt = (nv & 1) ? 1.0f : 0.5f;              // nv even -> 0.5
    }
#pragma unroll
    for (int df = 0; df < 8; df++) {
      const int col = 1024 + h * 64 + df * 8 + 2 * tg;
      __nv_bfloat162 v0 = __floats2bfloat162_rn(wgt * o[df][0] * i0, wgt * o[df][1] * i0);
      __nv_bfloat162 v1 = __floats2bfloat162_rn(wgt * o[df][2] * i1, wgt * o[df][3] * i1);
      atomicAdd((__nv_bfloat162*)&g_ATT[(size_t)t0 * ATTN + col], v0);
      atomicAdd((__nv_bfloat162*)&g_ATT[(size_t)t1 * ATTN + col], v1);
    }
  }
}

// ---------------------------------------------------------------------------
extern "C" void kernel_launch(void* const* d_in, const int* in_sizes, int n_in,
                              void* d_out, int out_size) {
  (void)in_sizes; (void)n_in; (void)out_size;
  const float* x   = (const float*)d_in[0];
  const float* Wq  = (const float*)d_in[1];
  const float* Wk  = (const float*)d_in[2];
  const float* Wv  = (const float*)d_in[3];
  const float* Wo  = (const float*)d_in[4];
  const float* bo  = (const float*)d_in[5];
  const float* Wqm = (const float*)d_in[6];
  const float* Wkm = (const float*)d_in[7];
  const float* Wvm = (const float*)d_in[8];
  const float* Wom = (const float*)d_in[9];
  const float* bom = (const float*)d_in[10];
  float* out = (float*)d_out;

  cudaFuncSetAttribute(gemm_mma<DMODEL, 0>,
                       cudaFuncAttributeMaxDynamicSharedMemorySize, GSMEM);
  cudaFuncSetAttribute(gemm_mma<ATTN, 1>,
                       cudaFuncAttributeMaxDynamicSharedMemorySize, GSMEM);

  Ptr6 W6;
  W6.p[0] = Wq;  W6.p[1] = Wk;  W6.p[2] = Wv;
  W6.p[3] = Wqm; W6.p[4] = Wkm; W6.p[5] = Wvm;

  prep_all<<<NALL / 256, 256>>>((const float4*)x, W6,
                                (const float4*)Wo, (const float4*)Wom);
  gemm_mma<DMODEL, 0><<<dim3(QKVN / 256, TOK / 128), 256, GSMEM>>>(
      nullptr, nullptr, nullptr, nullptr);
  attn_all<<<7168, 128>>>();
  gemm_mma<ATTN, 1><<<dim3(DMODEL / 256, TOK / 128), 256, GSMEM>>>(
      bo, bom, x, out);
}

// round 12
// speedup vs baseline: 1.0871x; 1.0168x over previous
#include <cuda_runtime.h>
#include <cuda_bf16.h>
#include <cstdint>
#include <cstddef>

#define TOK    12288
#define DMODEL 1024
#define QKVN   6144
#define ATTN   2048

// Scratch (static device globals per harness rules)
static __device__ __nv_bfloat16 g_QKV[(size_t)TOK * QKVN];    // GEMM1 out
static __device__ __nv_bfloat16 g_ATT[(size_t)TOK * ATTN];    // attn out (GEMM2 A)
static __device__ __nv_bfloat16 g_W16[(size_t)QKVN * DMODEL]; // [Wq;Wk;Wv;Wqm;Wkm;Wvm]
static __device__ __nv_bfloat16 g_WO16[(size_t)DMODEL * ATTN];// row n: [Wo[n,:]|Wom[n,:]]

struct Ptr6 { const float* p[6]; };

// ---------------------------------------------------------------------------
// helpers
// ---------------------------------------------------------------------------
__device__ __forceinline__ unsigned pack_bf2(float lo, float hi) {
  unsigned d;
  asm("cvt.rn.bf16x2.f32 %0, %1, %2;" : "=r"(d) : "f"(hi), "f"(lo));
  return d;
}
__device__ __forceinline__ unsigned smem_u32(const void* p) {
  return (unsigned)__cvta_generic_to_shared(p);
}
__device__ __forceinline__ void ldm_x4(unsigned* r, unsigned addr) {
  asm volatile("ldmatrix.sync.aligned.m8n8.x4.shared.b16 {%0,%1,%2,%3}, [%4];"
               : "=r"(r[0]), "=r"(r[1]), "=r"(r[2]), "=r"(r[3]) : "r"(addr));
}
__device__ __forceinline__ void ldm_x4t(unsigned* r, unsigned addr) {
  asm volatile("ldmatrix.sync.aligned.m8n8.x4.trans.shared.b16 {%0,%1,%2,%3}, [%4];"
               : "=r"(r[0]), "=r"(r[1]), "=r"(r[2]), "=r"(r[3]) : "r"(addr));
}
__device__ __forceinline__ void mma_bf16(float* d, const unsigned* a,
                                         const unsigned* b, const float* c) {
  asm volatile(
      "mma.sync.aligned.m16n8k16.row.col.f32.bf16.bf16.f32 "
      "{%0,%1,%2,%3}, {%4,%5,%6,%7}, {%8,%9}, {%10,%11,%12,%13};"
      : "=f"(d[0]), "=f"(d[1]), "=f"(d[2]), "=f"(d[3])
      : "r"(a[0]), "r"(a[1]), "r"(a[2]), "r"(a[3]), "r"(b[0]), "r"(b[1]),
        "f"(c[0]), "f"(c[1]), "f"(c[2]), "f"(c[3]));
}
__device__ __forceinline__ void cpa16(unsigned dst, const void* src) {
  asm volatile("cp.async.cg.shared.global [%0], [%1], 16;" :: "r"(dst), "l"(src)
               : "memory");
}

// ---------------------------------------------------------------------------
// Fused prep kernel: weight conversions + zero-init of g_ATT mv half.
// (x is no longer pre-converted: GEMM1 loads f32 x directly.)
// ---------------------------------------------------------------------------
#define NW  (QKVN * DMODEL / 4)         // 6291456
#define NWO (DMODEL * DMODEL / 4)       // 262144
#define NZ  (TOK * 1024 / 8)            // 1572864
#define NALL (NW + NWO + NZ)            // 8126464 -> 31744 blocks of 256

__global__ void prep_all(Ptr6 W, const float4* __restrict__ Wo,
                         const float4* __restrict__ Wom) {
  int i = blockIdx.x * 256 + threadIdx.x;
  if (i < NW) {
    int row = i >> 8;                                 // 256 float4 per row
    const float4* src = (const float4*)W.p[row >> 10];
    float4 v = src[((row & 1023) << 8) + (i & 255)];
    ((uint2*)g_W16)[i] = make_uint2(pack_bf2(v.x, v.y), pack_bf2(v.z, v.w));
  } else if (i < NW + NWO) {
    int j = i - NW;
    int row = j >> 8, c = j & 255;
    float4 a = Wo[j], b = Wom[j];
    uint2* dst = (uint2*)g_WO16;
    dst[row * 512 + c]       = make_uint2(pack_bf2(a.x, a.y), pack_bf2(a.z, a.w));
    dst[row * 512 + 256 + c] = make_uint2(pack_bf2(b.x, b.y), pack_bf2(b.z, b.w));
  } else {
    int j = i - NW - NWO;
    int row = j >> 7, c = (j & 127) * 8;
    *(uint4*)&g_ATT[(size_t)row * ATTN + 1024 + c] = make_uint4(0, 0, 0, 0);
  }
}

// ---------------------------------------------------------------------------
// GEMM (bf16 mma.sync, multistage) — R7 core.
// CTA tile 128x256, BK=32, 4 stages, 256 threads (8 warps, 64x64 warp tile).
// MODE 0: A = x (f32! LDG+cvt+STS), B=g_W16 (cp.async) -> bf16 g_QKV
// MODE 1: A = g_ATT (cp.async),     B=g_WO16 (cp.async)-> f32 Out=acc+bias+x
// ---------------------------------------------------------------------------
#define BPITCH  40
#define STAGES  4
#define STG_ELM ((128 + 256) * BPITCH)            // bf16 per stage = 15360
#define GSMEM   (STAGES * STG_ELM * 2)            // 122880 B

template <int K, int MODE>
__global__ __launch_bounds__(256) void gemm_mma(
    const float* __restrict__ bo, const float* __restrict__ bom,
    const float* __restrict__ X, float* __restrict__ Out) {
  extern __shared__ __align__(16) __nv_bfloat16 sm[];
  const int tid = threadIdx.x;
  const int m0 = blockIdx.y * 128, n0 = blockIdx.x * 256;
  const __nv_bfloat16* __restrict__ Bm = (MODE == 0) ? g_W16 : g_WO16;
  const int lane = tid & 31, wid = tid >> 5;
  const int wm = (wid & 1) * 64, wn = (wid >> 1) * 64;
  const int g = lane >> 2, tg = lane & 3;

  // B loader: 256x32 bf16 = 1024 x16B chunks, 4/thread (cp.async)
  auto load_B = [&](int k0, int s) {
    __nv_bfloat16* stg = sm + s * STG_ELM + 128 * BPITCH;
#pragma unroll
    for (int j = 0; j < 4; j++) {
      const int idx = tid + j * 256;
      const int row = idx >> 2, c = (idx & 3) * 8;
      cpa16(smem_u32(&stg[row * BPITCH + c]),
            &Bm[(size_t)(n0 + row) * K + k0 + c]);
    }
  };
  // MODE 0 A path: f32 LDG (4 float4/thread) + cvt + STS
  auto ldg_A = [&](int k0, float4* av) {
#pragma unroll
    for (int j = 0; j < 4; j++) {
      const int idx = tid + j * 256;
      const int row = idx >> 3, c4 = (idx & 7) * 4;
      av[j] = *(const float4*)&X[(size_t)(m0 + row) * K + k0 + c4];
    }
  };
  auto sts_A = [&](int s, const float4* av) {
    __nv_bfloat16* stg = sm + s * STG_ELM;
#pragma unroll
    for (int j = 0; j < 4; j++) {
      const int idx = tid + j * 256;
      const int row = idx >> 3, c4 = (idx & 7) * 4;
      *(uint2*)&stg[row * BPITCH + c4] =
          make_uint2(pack_bf2(av[j].x, av[j].y), pack_bf2(av[j].z, av[j].w));
    }
  };
  // MODE 1 A path: bf16 cp.async (128x32 = 512 chunks, 2/thread)
  auto cpa_A = [&](int k0, int s) {
    __nv_bfloat16* stg = sm + s * STG_ELM;
#pragma unroll
    for (int j = 0; j < 2; j++) {
      const int idx = tid + j * 256;
      const int row = idx >> 2, c = (idx & 3) * 8;
      cpa16(smem_u32(&stg[row * BPITCH + c]),
            &g_ATT[(size_t)(m0 + row) * K + k0 + c]);
    }
  };

  float acc[4][8][4];
#pragma unroll
  for (int mi = 0; mi < 4; mi++)
#pragma unroll
    for (int ni = 0; ni < 8; ni++)
#pragma unroll
      for (int r = 0; r < 4; r++) acc[mi][ni][r] = 0.f;

  constexpr int NC = K / 32;
  // prologue: 3 stages
#pragma unroll
  for (int s = 0; s < STAGES - 1; s++) {
    if (MODE == 0) {
      float4 av[4];
      ldg_A(s * 32, av);
      sts_A(s, av);
    } else {
      cpa_A(s * 32, s);
    }
    load_B(s * 32, s);
    asm volatile("cp.async.commit_group;" ::: "memory");
  }

#pragma unroll 1
  for (int kc = 0; kc < NC; kc++) {
    asm volatile("cp.async.wait_group %0;" :: "n"(STAGES - 2) : "memory");
    __syncthreads();
    const bool pre = (kc + STAGES - 1 < NC);
    const int ps = (kc + STAGES - 1) % STAGES;
    float4 av[4];
    if (pre) {
      if (MODE == 0) ldg_A((kc + STAGES - 1) * 32, av);
      else cpa_A((kc + STAGES - 1) * 32, ps);
      load_B((kc + STAGES - 1) * 32, ps);
    }
    asm volatile("cp.async.commit_group;" ::: "memory");

    const int s = kc % STAGES;
    const unsigned as = smem_u32(sm + s * STG_ELM);
    const unsigned bs = as + 128 * BPITCH * 2;
#pragma unroll
    for (int ks = 0; ks < 2; ks++) {
      const int kk = ks * 16;
      unsigned afr[4][4];
#pragma unroll
      for (int mi = 0; mi < 4; mi++)
        ldm_x4(afr[mi],
               as + ((wm + mi * 16 + (lane & 15)) * BPITCH + kk + (lane >> 4) * 8) * 2);
#pragma unroll
      for (int n2 = 0; n2 < 4; n2++) {
        unsigned bfr[4];
        ldm_x4(bfr, bs + ((wn + n2 * 16 + (lane >> 4) * 8 + (lane & 7)) * BPITCH +
                          kk + ((lane >> 3) & 1) * 8) * 2);
#pragma unroll
        for (int mi = 0; mi < 4; mi++) {
          mma_bf16(acc[mi][2 * n2], afr[mi], bfr, acc[mi][2 * n2]);
          mma_bf16(acc[mi][2 * n2 + 1], afr[mi], bfr + 2, acc[mi][2 * n2 + 1]);
        }
      }
    }
    if (MODE == 0 && pre) sts_A(ps, av);   // buffer ps freed at kc-1, sync at kc
  }

#pragma unroll
  for (int mi = 0; mi < 4; mi++)
#pragma unroll
    for (int ni = 0; ni < 8; ni++) {
      const int row = m0 + wm + mi * 16 + g;
      const int col = n0 + wn + ni * 8 + 2 * tg;
      if (MODE == 0) {
        *(unsigned*)&g_QKV[(size_t)row * QKVN + col] =
            pack_bf2(acc[mi][ni][0], acc[mi][ni][1]);
        *(unsigned*)&g_QKV[(size_t)(row + 8) * QKVN + col] =
            pack_bf2(acc[mi][ni][2], acc[mi][ni][3]);
      } else {
        const float bias0 = bo[col] + bom[col];
        const float bias1 = bo[col + 1] + bom[col + 1];
        float2 x0 = *(const float2*)&X[(size_t)row * DMODEL + col];
        float2 x1 = *(const float2*)&X[(size_t)(row + 8) * DMODEL + col];
        *(float2*)&Out[(size_t)row * DMODEL + col] =
            make_float2(acc[mi][ni][0] + bias0 + x0.x, acc[mi][ni][1] + bias1 + x0.y);
        *(float2*)&Out[(size_t)(row + 8) * DMODEL + col] =
            make_float2(acc[mi][ni][2] + bias0 + x1.x, acc[mi][ni][3] + bias1 + x1.y);
      }
    }
}

// ---------------------------------------------------------------------------
// Fused flash attention (main + col + row), K/V double-buffered via cp.async.
//   blockIdx.x [0,3072): main | [3072,5120): col | [5120,7168): row
// ---------------------------------------------------------------------------
#define APITCH 72

__device__ __forceinline__ int mv_token(int bb, int j, int ij, int is_col) {
  int c = j >> 5, pos = j & 31;
  int nv = is_col ? ((c < 3) ? 2 * c : 5) : c;  // COL_IDX = {0,2,4,5}
  int s  = is_col ? (pos * 32 + ij) : (ij * 32 + pos);
  return (bb * 6 + nv) * 1024 + s;
}

__device__ __forceinline__ void fa_tile(
    unsigned qsm, unsigned ksm, unsigned vsm, int lane, int wrow,
    float& m0v, float& m1v, float& l0, float& l1, float o[8][4]) {
  const int half = (lane >> 3) & 1, quad = lane >> 4;
  float s[8][4];
#pragma unroll
  for (int nf = 0; nf < 8; nf++)
#pragma unroll
    for (int r = 0; r < 4; r++) s[nf][r] = 0.f;
#pragma unroll
  for (int kcc = 0; kcc < 4; kcc++) {
    unsigned a[4];
    ldm_x4(a, qsm + ((wrow + (lane & 15)) * APITCH + kcc * 16 + quad * 8) * 2);
#pragma unroll
    for (int n2 = 0; n2 < 4; n2++) {
      unsigned bf[4];
      ldm_x4(bf, ksm + ((n2 * 16 + quad * 8 + (lane & 7)) * APITCH + kcc * 16 + half * 8) * 2);
      mma_bf16(s[2 * n2], a, bf, s[2 * n2]);
      mma_bf16(s[2 * n2 + 1], a, bf + 2, s[2 * n2 + 1]);
    }
  }
  float mx0 = -1e30f, mx1 = -1e30f;
#pragma unroll
  for (int nf = 0; nf < 8; nf++) {
#pragma unroll
    for (int r = 0; r < 4; r++) s[nf][r] *= 0.125f;
    mx0 = fmaxf(mx0, fmaxf(s[nf][0], s[nf][1]));
    mx1 = fmaxf(mx1, fmaxf(s[nf][2], s[nf][3]));
  }
  mx0 = fmaxf(mx0, __shfl_xor_sync(0xffffffffu, mx0, 1));
  mx0 = fmaxf(mx0, __shfl_xor_sync(0xffffffffu, mx0, 2));
  mx1 = fmaxf(mx1, __shfl_xor_sync(0xffffffffu, mx1, 1));
  mx1 = fmaxf(mx1, __shfl_xor_sync(0xffffffffu, mx1, 2));
  const float nm0 = fmaxf(m0v, mx0), nm1 = fmaxf(m1v, mx1);
  const float c0 = __expf(m0v - nm0), c1 = __expf(m1v - nm1);
  m0v = nm0; m1v = nm1;
  float sum0 = 0.f, sum1 = 0.f;
  unsigned pa[4][4];
#pragma unroll
  for (int j = 0; j < 4; j++) {
    float p00 = __expf(s[2 * j][0] - nm0), p01 = __expf(s[2 * j][1] - nm0);
    float p02 = __expf(s[2 * j][2] - nm1), p03 = __expf(s[2 * j][3] - nm1);
    float p10 = __expf(s[2 * j + 1][0] - nm0), p11 = __expf(s[2 * j + 1][1] - nm0);
    float p12 = __expf(s[2 * j + 1][2] - nm1), p13 = __expf(s[2 * j + 1][3] - nm1);
    pa[j][0] = pack_bf2(p00, p01);
    pa[j][1] = pack_bf2(p02, p03);
    pa[j][2] = pack_bf2(p10, p11);
    pa[j][3] = pack_bf2(p12, p13);
    sum0 += p00 + p01 + p10 + p11;
    sum1 += p02 + p03 + p12 + p13;
  }
  sum0 += __shfl_xor_sync(0xffffffffu, sum0, 1);
  sum0 += __shfl_xor_sync(0xffffffffu, sum0, 2);
  sum1 += __shfl_xor_sync(0xffffffffu, sum1, 1);
  sum1 += __shfl_xor_sync(0xffffffffu, sum1, 2);
  l0 = l0 * c0 + sum0;
  l1 = l1 * c1 + sum1;
#pragma unroll
  for (int df = 0; df < 8; df++) {
    o[df][0] *= c0; o[df][1] *= c0; o[df][2] *= c1; o[df][3] *= c1;
  }
#pragma unroll
  for (int j = 0; j < 4; j++)
#pragma unroll
    for (int d2 = 0; d2 < 4; d2++) {
      unsigned bf[4];
      ldm_x4t(bf, vsm + ((j * 16 + half * 8 + (lane & 7)) * APITCH + d2 * 16 + quad * 8) * 2);
      mma_bf16(o[2 * d2], pa[j], bf, o[2 * d2]);
      mma_bf16(o[2 * d2 + 1], pa[j], bf + 2, o[2 * d2 + 1]);
    }
}

__global__ __launch_bounds__(128) void attn_all() {
  __shared__ __align__(16) __nv_bfloat16 Qs[64 * APITCH];
  __shared__ __align__(16) __nv_bfloat16 Ks[2][64 * APITCH];
  __shared__ __align__(16) __nv_bfloat16 Vs[2][64 * APITCH];
  const int tid = threadIdx.x, lane = tid & 31, w = tid >> 5;
  const int bx = blockIdx.x;

  const int role = (bx < 3072) ? 0 : (bx < 5120) ? 1 : 2;  // 0=main 1=col 2=row
  int qt, h, bb, ij, tb = 0;
  if (role == 0) {
    qt = bx & 15;
    const int by = bx >> 4;
    h = by & 15;
    tb = (by >> 4) << 10;
    bb = 0; ij = 0;
  } else {
    const int u = bx - (role == 1 ? 3072 : 5120);
    qt = u & 1;
    const int gy = u >> 1;
    h = gy & 15;
    ij = (gy >> 4) & 31;
    bb = gy >> 9;
  }
  const int is_col = (role == 1);
  const int colQ = (role == 0 ? 0 : 3072) + h * 64;
  const int colK = colQ + 1024;
  const int colV = colQ + 2048;
  const int ktmax = (role == 0) ? 16 : 2;

  auto ktoken = [&](int kt, int r) -> int {
    return (role == 0) ? (tb + kt * 64 + r) : mv_token(bb, kt * 64 + r, ij, is_col);
  };

  // K/V stage loader: 512 chunks K + 512 chunks V, 8 cpa/thread
  auto load_kv = [&](int kt, int s) {
#pragma unroll
    for (int i = 0; i < 8; i++) {
      const int idx = tid + i * 128;
      const int r = (idx >> 3) & 63;
      const int c8 = (idx & 7) * 8;
      const size_t trow = (size_t)ktoken(kt, r) * QKVN;
      if (idx < 512)
        cpa16(smem_u32(&Ks[s][r * APITCH + c8]), &g_QKV[trow + colK + c8]);
      else
        cpa16(smem_u32(&Vs[s][r * APITCH + c8]), &g_QKV[trow + colV + c8]);
    }
  };

  // Q load (direct)
#pragma unroll
  for (int i = 0; i < 4; i++) {
    int u = tid + i * 128;
    int r = u >> 3, o8 = (u & 7) * 8;
    *(uint4*)&Qs[r * APITCH + o8] =
        *(const uint4*)&g_QKV[(size_t)ktoken(0, 0) * 0 +
                              (size_t)((role == 0) ? (tb + qt * 64 + r)
                                                   : mv_token(bb, qt * 64 + r, ij, is_col)) *
                                  QKVN + colQ + o8];
  }
  const int g = lane >> 2, tg = lane & 3;
  const int wrow = w * 16;
  float m0v = -1e30f, m1v = -1e30f, l0 = 0.f, l1 = 0.f;
  float o[8][4];
#pragma unroll
  for (int df = 0; df < 8; df++)
#pragma unroll
    for (int r = 0; r < 4; r++) o[df][r] = 0.f;
  const unsigned qsm = smem_u32(Qs);

  load_kv(0, 0);
  asm volatile("cp.async.commit_group;" ::: "memory");

#pragma unroll 1
  for (int kt = 0; kt < ktmax; kt++) {
    asm volatile("cp.async.wait_group 0;" ::: "memory");
    __syncthreads();               // stage kt visible; stage kt^1 free (fa done)
    if (kt + 1 < ktmax) load_kv(kt + 1, (kt + 1) & 1);
    asm volatile("cp.async.commit_group;" ::: "memory");
    const int s = kt & 1;
    fa_tile(qsm, smem_u32(Ks[s]), smem_u32(Vs[s]), lane, wrow, m0v, m1v, l0, l1, o);
    __syncthreads();               // fa_tile(kt) done before stage s refill at kt+2
  }

  const float i0 = 1.f / l0, i1 = 1.f / l1;
  if (role == 0) {
    const int row = tb + qt * 64 + wrow + g;
#pragma unroll
    for (int df = 0; df < 8; df++) {
      const int col = h * 64 + df * 8 + 2 * tg;
      *(unsigned*)&g_ATT[(size_t)row * ATTN + col] =
          pack_bf2(o[df][0] * i0, o[df][1] * i0);
      *(unsigned*)&g_ATT[(size_t)(row + 8) * ATTN + col] =
          pack_bf2(o[df][2] * i1, o[df][3] * i1);
    }
  } else {
    const int t0 = mv_token(bb, qt * 64 + wrow + g, ij, is_col);
    const int t1 = mv_token(bb, qt * 64 + wrow + g + 8, ij, is_col);
    float wgt;
    if (is_col) {
      wgt = (qt == 0) ? 0.5f : 1.0f;
    } else {
      const int nv = 2 * qt + (w >> 1);
      wgt = (nv & 1) ? 1.0f : 0.5f;
    }
#pragma unroll
    for (int df = 0; df < 8; df++) {
      const int col = 1024 + h * 64 + df * 8 + 2 * tg;
      __nv_bfloat162 v0 = __floats2bfloat162_rn(wgt * o[df][0] * i0, wgt * o[df][1] * i0);
      __nv_bfloat162 v1 = __floats2bfloat162_rn(wgt * o[df][2] * i1, wgt * o[df][3] * i1);
      atomicAdd((__nv_bfloat162*)&g_ATT[(size_t)t0 * ATTN + col], v0);
      atomicAdd((__nv_bfloat162*)&g_ATT[(size_t)t1 * ATTN + col], v1);
    }
  }
}

// ---------------------------------------------------------------------------
extern "C" void kernel_launch(void* const* d_in, const int* in_sizes, int n_in,
                              void* d_out, int out_size) {
  (void)in_sizes; (void)n_in; (void)out_size;
  const float* x   = (const float*)d_in[0];
  const float* Wq  = (const float*)d_in[1];
  const float* Wk  = (const float*)d_in[2];
  const float* Wv  = (const float*)d_in[3];
  const float* Wo  = (const float*)d_in[4];
  const float* bo  = (const float*)d_in[5];
  const float* Wqm = (const float*)d_in[6];
  const float* Wkm = (const float*)d_in[7];
  const float* Wvm = (const float*)d_in[8];
  const float* Wom = (const float*)d_in[9];
  const float* bom = (const float*)d_in[10];
  float* out = (float*)d_out;

  cudaFuncSetAttribute(gemm_mma<DMODEL, 0>,
                       cudaFuncAttributeMaxDynamicSharedMemorySize, GSMEM);
  cudaFuncSetAttribute(gemm_mma<ATTN, 1>,
                       cudaFuncAttributeMaxDynamicSharedMemorySize, GSMEM);

  Ptr6 W6;
  W6.p[0] = Wq;  W6.p[1] = Wk;  W6.p[2] = Wv;
  W6.p[3] = Wqm; W6.p[4] = Wkm; W6.p[5] = Wvm;

  prep_all<<<NALL / 256, 256>>>(W6, (const float4*)Wo, (const float4*)Wom);
  gemm_mma<DMODEL, 0><<<dim3(QKVN / 256, TOK / 128), 256, GSMEM>>>(
      nullptr, nullptr, x, nullptr);
  attn_all<<<7168, 128>>>();
  gemm_mma<ATTN, 1><<<dim3(DMODEL / 256, TOK / 128), 256, GSMEM>>>(
      bo, bom, x, out);
}

// round 13
// speedup vs baseline: 1.1421x; 1.0507x over previous
#include <cuda_runtime.h>
#include <cuda_bf16.h>
#include <cstdint>
#include <cstddef>

#define TOK    12288
#define DMODEL 1024
#define QKVN   6144
#define ATTN   2048

// Scratch (static device globals per harness rules)
static __device__ __nv_bfloat16 g_QKV[(size_t)TOK * QKVN];    // GEMM1 out
static __device__ __nv_bfloat16 g_ATT[(size_t)TOK * ATTN];    // attn out (GEMM2 A)
static __device__ __nv_bfloat16 g_W16[(size_t)QKVN * DMODEL]; // [Wq;Wk;Wv;Wqm;Wkm;Wvm]
static __device__ __nv_bfloat16 g_WO16[(size_t)DMODEL * ATTN];// row n: [Wo[n,:]|Wom[n,:]]

struct Ptr6 { const float* p[6]; };

// ---------------------------------------------------------------------------
// helpers
// ---------------------------------------------------------------------------
__device__ __forceinline__ unsigned pack_bf2(float lo, float hi) {
  unsigned d;
  asm("cvt.rn.bf16x2.f32 %0, %1, %2;" : "=r"(d) : "f"(hi), "f"(lo));
  return d;
}
__device__ __forceinline__ unsigned smem_u32(const void* p) {
  return (unsigned)__cvta_generic_to_shared(p);
}
__device__ __forceinline__ void ldm_x4(unsigned* r, unsigned addr) {
  asm volatile("ldmatrix.sync.aligned.m8n8.x4.shared.b16 {%0,%1,%2,%3}, [%4];"
               : "=r"(r[0]), "=r"(r[1]), "=r"(r[2]), "=r"(r[3]) : "r"(addr));
}
__device__ __forceinline__ void ldm_x4t(unsigned* r, unsigned addr) {
  asm volatile("ldmatrix.sync.aligned.m8n8.x4.trans.shared.b16 {%0,%1,%2,%3}, [%4];"
               : "=r"(r[0]), "=r"(r[1]), "=r"(r[2]), "=r"(r[3]) : "r"(addr));
}
__device__ __forceinline__ void mma_bf16(float* d, const unsigned* a,
                                         const unsigned* b, const float* c) {
  asm volatile(
      "mma.sync.aligned.m16n8k16.row.col.f32.bf16.bf16.f32 "
      "{%0,%1,%2,%3}, {%4,%5,%6,%7}, {%8,%9}, {%10,%11,%12,%13};"
      : "=f"(d[0]), "=f"(d[1]), "=f"(d[2]), "=f"(d[3])
      : "r"(a[0]), "r"(a[1]), "r"(a[2]), "r"(a[3]), "r"(b[0]), "r"(b[1]),
        "f"(c[0]), "f"(c[1]), "f"(c[2]), "f"(c[3]));
}
__device__ __forceinline__ void cpa16(unsigned dst, const void* src) {
  asm volatile("cp.async.cg.shared.global [%0], [%1], 16;" :: "r"(dst), "l"(src)
               : "memory");
}

// ---------------------------------------------------------------------------
// Fused prep kernel: weight conversions + zero-init of g_ATT mv half.
// ---------------------------------------------------------------------------
#define NW  (QKVN * DMODEL / 4)         // 6291456
#define NWO (DMODEL * DMODEL / 4)       // 262144
#define NZ  (TOK * 1024 / 8)            // 1572864
#define NALL (NW + NWO + NZ)            // 8126464 -> 31744 blocks of 256

__global__ void prep_all(Ptr6 W, const float4* __restrict__ Wo,
                         const float4* __restrict__ Wom) {
  int i = blockIdx.x * 256 + threadIdx.x;
  if (i < NW) {
    int row = i >> 8;
    const float4* src = (const float4*)W.p[row >> 10];
    float4 v = src[((row & 1023) << 8) + (i & 255)];
    ((uint2*)g_W16)[i] = make_uint2(pack_bf2(v.x, v.y), pack_bf2(v.z, v.w));
  } else if (i < NW + NWO) {
    int j = i - NW;
    int row = j >> 8, c = j & 255;
    float4 a = Wo[j], b = Wom[j];
    uint2* dst = (uint2*)g_WO16;
    dst[row * 512 + c]       = make_uint2(pack_bf2(a.x, a.y), pack_bf2(a.z, a.w));
    dst[row * 512 + 256 + c] = make_uint2(pack_bf2(b.x, b.y), pack_bf2(b.z, b.w));
  } else {
    int j = i - NW - NWO;
    int row = j >> 7, c = (j & 127) * 8;
    *(uint4*)&g_ATT[(size_t)row * ATTN + 1024 + c] = make_uint4(0, 0, 0, 0);
  }
}

// ---------------------------------------------------------------------------
// GEMM1 (bf16 mma.sync, multistage) — unchanged R12 MODE 0.
// CTA tile 128x256, BK=32, 4 stages, 256 threads (8 warps, 64x64 warp tile).
// A = x (f32 LDG+cvt+STS), B = g_W16 (cp.async) -> bf16 g_QKV
// ---------------------------------------------------------------------------
#define BPITCH  40
#define STAGES  4
#define STG_ELM ((128 + 256) * BPITCH)            // 15360
#define GSMEM   (STAGES * STG_ELM * 2)            // 122880 B

__global__ __launch_bounds__(256) void gemm_qkv(const float* __restrict__ X) {
  extern __shared__ __align__(16) __nv_bfloat16 sm[];
  const int tid = threadIdx.x;
  const int m0 = blockIdx.y * 128, n0 = blockIdx.x * 256;
  constexpr int K = DMODEL;
  const int lane = tid & 31, wid = tid >> 5;
  const int wm = (wid & 1) * 64, wn = (wid >> 1) * 64;
  const int g = lane >> 2, tg = lane & 3;

  auto load_B = [&](int k0, int s) {
    __nv_bfloat16* stg = sm + s * STG_ELM + 128 * BPITCH;
#pragma unroll
    for (int j = 0; j < 4; j++) {
      const int idx = tid + j * 256;
      const int row = idx >> 2, c = (idx & 3) * 8;
      cpa16(smem_u32(&stg[row * BPITCH + c]),
            &g_W16[(size_t)(n0 + row) * K + k0 + c]);
    }
  };
  auto ldg_A = [&](int k0, float4* av) {
#pragma unroll
    for (int j = 0; j < 4; j++) {
      const int idx = tid + j * 256;
      const int row = idx >> 3, c4 = (idx & 7) * 4;
      av[j] = *(const float4*)&X[(size_t)(m0 + row) * K + k0 + c4];
    }
  };
  auto sts_A = [&](int s, const float4* av) {
    __nv_bfloat16* stg = sm + s * STG_ELM;
#pragma unroll
    for (int j = 0; j < 4; j++) {
      const int idx = tid + j * 256;
      const int row = idx >> 3, c4 = (idx & 7) * 4;
      *(uint2*)&stg[row * BPITCH + c4] =
          make_uint2(pack_bf2(av[j].x, av[j].y), pack_bf2(av[j].z, av[j].w));
    }
  };

  float acc[4][8][4];
#pragma unroll
  for (int mi = 0; mi < 4; mi++)
#pragma unroll
    for (int ni = 0; ni < 8; ni++)
#pragma unroll
      for (int r = 0; r < 4; r++) acc[mi][ni][r] = 0.f;

  constexpr int NC = K / 32;
#pragma unroll
  for (int s = 0; s < STAGES - 1; s++) {
    float4 av[4];
    ldg_A(s * 32, av);
    sts_A(s, av);
    load_B(s * 32, s);
    asm volatile("cp.async.commit_group;" ::: "memory");
  }

#pragma unroll 1
  for (int kc = 0; kc < NC; kc++) {
    asm volatile("cp.async.wait_group %0;" :: "n"(STAGES - 2) : "memory");
    __syncthreads();
    const bool pre = (kc + STAGES - 1 < NC);
    const int ps = (kc + STAGES - 1) % STAGES;
    float4 av[4];
    if (pre) {
      ldg_A((kc + STAGES - 1) * 32, av);
      load_B((kc + STAGES - 1) * 32, ps);
    }
    asm volatile("cp.async.commit_group;" ::: "memory");

    const int s = kc % STAGES;
    const unsigned as = smem_u32(sm + s * STG_ELM);
    const unsigned bs = as + 128 * BPITCH * 2;
#pragma unroll
    for (int ks = 0; ks < 2; ks++) {
      const int kk = ks * 16;
      unsigned afr[4][4];
#pragma unroll
      for (int mi = 0; mi < 4; mi++)
        ldm_x4(afr[mi],
               as + ((wm + mi * 16 + (lane & 15)) * BPITCH + kk + (lane >> 4) * 8) * 2);
#pragma unroll
      for (int n2 = 0; n2 < 4; n2++) {
        unsigned bfr[4];
        ldm_x4(bfr, bs + ((wn + n2 * 16 + (lane >> 4) * 8 + (lane & 7)) * BPITCH +
                          kk + ((lane >> 3) & 1) * 8) * 2);
#pragma unroll
        for (int mi = 0; mi < 4; mi++) {
          mma_bf16(acc[mi][2 * n2], afr[mi], bfr, acc[mi][2 * n2]);
          mma_bf16(acc[mi][2 * n2 + 1], afr[mi], bfr + 2, acc[mi][2 * n2 + 1]);
        }
      }
    }
    if (pre) sts_A(ps, av);
  }

#pragma unroll
  for (int mi = 0; mi < 4; mi++)
#pragma unroll
    for (int ni = 0; ni < 8; ni++) {
      const int row = m0 + wm + mi * 16 + g;
      const int col = n0 + wn + ni * 8 + 2 * tg;
      *(unsigned*)&g_QKV[(size_t)row * QKVN + col] =
          pack_bf2(acc[mi][ni][0], acc[mi][ni][1]);
      *(unsigned*)&g_QKV[(size_t)(row + 8) * QKVN + col] =
          pack_bf2(acc[mi][ni][2], acc[mi][ni][3]);
    }
}

// ---------------------------------------------------------------------------
// GEMM2 (bf16 mma.sync): CTA tile 128x128, BK=32, 4 stages, 256 threads
// (8 warps, 64x32 warp tiles). 2 CTAs/SM co-resident (smem 80KB, regs<128)
// to eliminate the 2.59-wave quantization of the 128x256 version.
// Out = acc + bo + bom + X
// ---------------------------------------------------------------------------
#define STG2_ELM ((128 + 128) * BPITCH)           // 10240
#define GSMEM2   (STAGES * STG2_ELM * 2)          // 81920 B

__global__ __launch_bounds__(256, 2) void gemm_out128(
    const float* __restrict__ bo, const float* __restrict__ bom,
    const float* __restrict__ X, float* __restrict__ Out) {
  extern __shared__ __align__(16) __nv_bfloat16 sm[];
  const int tid = threadIdx.x;
  const int m0 = blockIdx.y * 128, n0 = blockIdx.x * 128;
  constexpr int K = ATTN;
  const int lane = tid & 31, wid = tid >> 5;
  const int wm = (wid & 1) * 64, wn = (wid >> 1) * 32;
  const int g = lane >> 2, tg = lane & 3;

  // stage loader: A 128x32 (512 chunks) + B 128x32 (512 chunks); 4/thread
  auto load_stage = [&](int k0, int s) {
    __nv_bfloat16* stg = sm + s * STG2_ELM;
#pragma unroll
    for (int j = 0; j < 4; j++) {
      const int idx = tid + j * 256;
      const int row = (idx >> 2) & 127, c = (idx & 3) * 8;
      if (idx < 512)
        cpa16(smem_u32(&stg[row * BPITCH + c]),
              &g_ATT[(size_t)(m0 + row) * K + k0 + c]);
      else
        cpa16(smem_u32(&stg[128 * BPITCH + row * BPITCH + c]),
              &g_WO16[(size_t)(n0 + row) * K + k0 + c]);
    }
  };

  float acc[4][4][4];
#pragma unroll
  for (int mi = 0; mi < 4; mi++)
#pragma unroll
    for (int ni = 0; ni < 4; ni++)
#pragma unroll
      for (int r = 0; r < 4; r++) acc[mi][ni][r] = 0.f;

  constexpr int NC = K / 32;
#pragma unroll
  for (int s = 0; s < STAGES - 1; s++) {
    load_stage(s * 32, s);
    asm volatile("cp.async.commit_group;" ::: "memory");
  }

#pragma unroll 1
  for (int kc = 0; kc < NC; kc++) {
    asm volatile("cp.async.wait_group %0;" :: "n"(STAGES - 2) : "memory");
    __syncthreads();
    if (kc + STAGES - 1 < NC)
      load_stage((kc + STAGES - 1) * 32, (kc + STAGES - 1) % STAGES);
    asm volatile("cp.async.commit_group;" ::: "memory");

    const int s = kc % STAGES;
    const unsigned as = smem_u32(sm + s * STG2_ELM);
    const unsigned bs = as + 128 * BPITCH * 2;
#pragma unroll
    for (int ks = 0; ks < 2; ks++) {
      const int kk = ks * 16;
      unsigned afr[4][4];
#pragma unroll
      for (int mi = 0; mi < 4; mi++)
        ldm_x4(afr[mi],
               as + ((wm + mi * 16 + (lane & 15)) * BPITCH + kk + (lane >> 4) * 8) * 2);
#pragma unroll
      for (int n2 = 0; n2 < 2; n2++) {
        unsigned bfr[4];
        ldm_x4(bfr, bs + ((wn + n2 * 16 + (lane >> 4) * 8 + (lane & 7)) * BPITCH +
                          kk + ((lane >> 3) & 1) * 8) * 2);
#pragma unroll
        for (int mi = 0; mi < 4; mi++) {
          mma_bf16(acc[mi][2 * n2], afr[mi], bfr, acc[mi][2 * n2]);
          mma_bf16(acc[mi][2 * n2 + 1], afr[mi], bfr + 2, acc[mi][2 * n2 + 1]);
        }
      }
    }
  }

#pragma unroll
  for (int mi = 0; mi < 4; mi++)
#pragma unroll
    for (int ni = 0; ni < 4; ni++) {
      const int row = m0 + wm + mi * 16 + g;
      const int col = n0 + wn + ni * 8 + 2 * tg;
      const float bias0 = bo[col] + bom[col];
      const float bias1 = bo[col + 1] + bom[col + 1];
      float2 x0 = *(const float2*)&X[(size_t)row * DMODEL + col];
      float2 x1 = *(const float2*)&X[(size_t)(row + 8) * DMODEL + col];
      *(float2*)&Out[(size_t)row * DMODEL + col] =
          make_float2(acc[mi][ni][0] + bias0 + x0.x, acc[mi][ni][1] + bias1 + x0.y);
      *(float2*)&Out[(size_t)(row + 8) * DMODEL + col] =
          make_float2(acc[mi][ni][2] + bias0 + x1.x, acc[mi][ni][3] + bias1 + x1.y);
    }
}

// ---------------------------------------------------------------------------
// Fused flash attention (main + col + row), K/V double-buffered — R12 code.
// ---------------------------------------------------------------------------
#define APITCH 72

__device__ __forceinline__ int mv_token(int bb, int j, int ij, int is_col) {
  int c = j >> 5, pos = j & 31;
  int nv = is_col ? ((c < 3) ? 2 * c : 5) : c;  // COL_IDX = {0,2,4,5}
  int s  = is_col ? (pos * 32 + ij) : (ij * 32 + pos);
  return (bb * 6 + nv) * 1024 + s;
}

__device__ __forceinline__ void fa_tile(
    unsigned qsm, unsigned ksm, unsigned vsm, int lane, int wrow,
    float& m0v, float& m1v, float& l0, float& l1, float o[8][4]) {
  const int half = (lane >> 3) & 1, quad = lane >> 4;
  float s[8][4];
#pragma unroll
  for (int nf = 0; nf < 8; nf++)
#pragma unroll
    for (int r = 0; r < 4; r++) s[nf][r] = 0.f;
#pragma unroll
  for (int kcc = 0; kcc < 4; kcc++) {
    unsigned a[4];
    ldm_x4(a, qsm + ((wrow + (lane & 15)) * APITCH + kcc * 16 + quad * 8) * 2);
#pragma unroll
    for (int n2 = 0; n2 < 4; n2++) {
      unsigned bf[4];
      ldm_x4(bf, ksm + ((n2 * 16 + quad * 8 + (lane & 7)) * APITCH + kcc * 16 + half * 8) * 2);
      mma_bf16(s[2 * n2], a, bf, s[2 * n2]);
      mma_bf16(s[2 * n2 + 1], a, bf + 2, s[2 * n2 + 1]);
    }
  }
  float mx0 = -1e30f, mx1 = -1e30f;
#pragma unroll
  for (int nf = 0; nf < 8; nf++) {
#pragma unroll
    for (int r = 0; r < 4; r++) s[nf][r] *= 0.125f;
    mx0 = fmaxf(mx0, fmaxf(s[nf][0], s[nf][1]));
    mx1 = fmaxf(mx1, fmaxf(s[nf][2], s[nf][3]));
  }
  mx0 = fmaxf(mx0, __shfl_xor_sync(0xffffffffu, mx0, 1));
  mx0 = fmaxf(mx0, __shfl_xor_sync(0xffffffffu, mx0, 2));
  mx1 = fmaxf(mx1, __shfl_xor_sync(0xffffffffu, mx1, 1));
  mx1 = fmaxf(mx1, __shfl_xor_sync(0xffffffffu, mx1, 2));
  const float nm0 = fmaxf(m0v, mx0), nm1 = fmaxf(m1v, mx1);
  const float c0 = __expf(m0v - nm0), c1 = __expf(m1v - nm1);
  m0v = nm0; m1v = nm1;
  float sum0 = 0.f, sum1 = 0.f;
  unsigned pa[4][4];
#pragma unroll
  for (int j = 0; j < 4; j++) {
    float p00 = __expf(s[2 * j][0] - nm0), p01 = __expf(s[2 * j][1] - nm0);
    float p02 = __expf(s[2 * j][2] - nm1), p03 = __expf(s[2 * j][3] - nm1);
    float p10 = __expf(s[2 * j + 1][0] - nm0), p11 = __expf(s[2 * j + 1][1] - nm0);
    float p12 = __expf(s[2 * j + 1][2] - nm1), p13 = __expf(s[2 * j + 1][3] - nm1);
    pa[j][0] = pack_bf2(p00, p01);
    pa[j][1] = pack_bf2(p02, p03);
    pa[j][2] = pack_bf2(p10, p11);
    pa[j][3] = pack_bf2(p12, p13);
    sum0 += p00 + p01 + p10 + p11;
    sum1 += p02 + p03 + p12 + p13;
  }
  sum0 += __shfl_xor_sync(0xffffffffu, sum0, 1);
  sum0 += __shfl_xor_sync(0xffffffffu, sum0, 2);
  sum1 += __shfl_xor_sync(0xffffffffu, sum1, 1);
  sum1 += __shfl_xor_sync(0xffffffffu, sum1, 2);
  l0 = l0 * c0 + sum0;
  l1 = l1 * c1 + sum1;
#pragma unroll
  for (int df = 0; df < 8; df++) {
    o[df][0] *= c0; o[df][1] *= c0; o[df][2] *= c1; o[df][3] *= c1;
  }
#pragma unroll
  for (int j = 0; j < 4; j++)
#pragma unroll
    for (int d2 = 0; d2 < 4; d2++) {
      unsigned bf[4];
      ldm_x4t(bf, vsm + ((j * 16 + half * 8 + (lane & 7)) * APITCH + d2 * 16 + quad * 8) * 2);
      mma_bf16(o[2 * d2], pa[j], bf, o[2 * d2]);
      mma_bf16(o[2 * d2 + 1], pa[j], bf + 2, o[2 * d2 + 1]);
    }
}

__global__ __launch_bounds__(128) void attn_all() {
  __shared__ __align__(16) __nv_bfloat16 Qs[64 * APITCH];
  __shared__ __align__(16) __nv_bfloat16 Ks[2][64 * APITCH];
  __shared__ __align__(16) __nv_bfloat16 Vs[2][64 * APITCH];
  const int tid = threadIdx.x, lane = tid & 31, w = tid >> 5;
  const int bx = blockIdx.x;

  const int role = (bx < 3072) ? 0 : (bx < 5120) ? 1 : 2;  // 0=main 1=col 2=row
  int qt, h, bb, ij, tb = 0;
  if (role == 0) {
    qt = bx & 15;
    const int by = bx >> 4;
    h = by & 15;
    tb = (by >> 4) << 10;
    bb = 0; ij = 0;
  } else {
    const int u = bx - (role == 1 ? 3072 : 5120);
    qt = u & 1;
    const int gy = u >> 1;
    h = gy & 15;
    ij = (gy >> 4) & 31;
    bb = gy >> 9;
  }
  const int is_col = (role == 1);
  const int colQ = (role == 0 ? 0 : 3072) + h * 64;
  const int colK = colQ + 1024;
  const int colV = colQ + 2048;
  const int ktmax = (role == 0) ? 16 : 2;

  auto ktoken = [&](int kt, int r) -> int {
    return (role == 0) ? (tb + kt * 64 + r) : mv_token(bb, kt * 64 + r, ij, is_col);
  };

  auto load_kv = [&](int kt, int s) {
#pragma unroll
    for (int i = 0; i < 8; i++) {
      const int idx = tid + i * 128;
      const int r = (idx >> 3) & 63;
      const int c8 = (idx & 7) * 8;
      const size_t trow = (size_t)ktoken(kt, r) * QKVN;
      if (idx < 512)
        cpa16(smem_u32(&Ks[s][r * APITCH + c8]), &g_QKV[trow + colK + c8]);
      else
        cpa16(smem_u32(&Vs[s][r * APITCH + c8]), &g_QKV[trow + colV + c8]);
    }
  };

#pragma unroll
  for (int i = 0; i < 4; i++) {
    int u = tid + i * 128;
    int r = u >> 3, o8 = (u & 7) * 8;
    int t = (role == 0) ? (tb + qt * 64 + r) : mv_token(bb, qt * 64 + r, ij, is_col);
    *(uint4*)&Qs[r * APITCH + o8] =
        *(const uint4*)&g_QKV[(size_t)t * QKVN + colQ + o8];
  }
  const int g = lane >> 2, tg = lane & 3;
  const int wrow = w * 16;
  float m0v = -1e30f, m1v = -1e30f, l0 = 0.f, l1 = 0.f;
  float o[8][4];
#pragma unroll
  for (int df = 0; df < 8; df++)
#pragma unroll
    for (int r = 0; r < 4; r++) o[df][r] = 0.f;
  const unsigned qsm = smem_u32(Qs);

  load_kv(0, 0);
  asm volatile("cp.async.commit_group;" ::: "memory");

#pragma unroll 1
  for (int kt = 0; kt < ktmax; kt++) {
    asm volatile("cp.async.wait_group 0;" ::: "memory");
    __syncthreads();
    if (kt + 1 < ktmax) load_kv(kt + 1, (kt + 1) & 1);
    asm volatile("cp.async.commit_group;" ::: "memory");
    const int s = kt & 1;
    fa_tile(qsm, smem_u32(Ks[s]), smem_u32(Vs[s]), lane, wrow, m0v, m1v, l0, l1, o);
    __syncthreads();
  }

  const float i0 = 1.f / l0, i1 = 1.f / l1;
  if (role == 0) {
    const int row = tb + qt * 64 + wrow + g;
#pragma unroll
    for (int df = 0; df < 8; df++) {
      const int col = h * 64 + df * 8 + 2 * tg;
      *(unsigned*)&g_ATT[(size_t)row * ATTN + col] =
          pack_bf2(o[df][0] * i0, o[df][1] * i0);
      *(unsigned*)&g_ATT[(size_t)(row + 8) * ATTN + col] =
          pack_bf2(o[df][2] * i1, o[df][3] * i1);
    }
  } else {
    const int t0 = mv_token(bb, qt * 64 + wrow + g, ij, is_col);
    const int t1 = mv_token(bb, qt * 64 + wrow + g + 8, ij, is_col);
    float wgt;
    if (is_col) {
      wgt = (qt == 0) ? 0.5f : 1.0f;
    } else {
      const int nv = 2 * qt + (w >> 1);
      wgt = (nv & 1) ? 1.0f : 0.5f;
    }
#pragma unroll
    for (int df = 0; df < 8; df++) {
      const int col = 1024 + h * 64 + df * 8 + 2 * tg;
      __nv_bfloat162 v0 = __floats2bfloat162_rn(wgt * o[df][0] * i0, wgt * o[df][1] * i0);
      __nv_bfloat162 v1 = __floats2bfloat162_rn(wgt * o[df][2] * i1, wgt * o[df][3] * i1);
      atomicAdd((__nv_bfloat162*)&g_ATT[(size_t)t0 * ATTN + col], v0);
      atomicAdd((__nv_bfloat162*)&g_ATT[(size_t)t1 * ATTN + col], v1);
    }
  }
}

// ---------------------------------------------------------------------------
extern "C" void kernel_launch(void* const* d_in, const int* in_sizes, int n_in,
                              void* d_out, int out_size) {
  (void)in_sizes; (void)n_in; (void)out_size;
  const float* x   = (const float*)d_in[0];
  const float* Wq  = (const float*)d_in[1];
  const float* Wk  = (const float*)d_in[2];
  const float* Wv  = (const float*)d_in[3];
  const float* Wo  = (const float*)d_in[4];
  const float* bo  = (const float*)d_in[5];
  const float* Wqm = (const float*)d_in[6];
  const float* Wkm = (const float*)d_in[7];
  const float* Wvm = (const float*)d_in[8];
  const float* Wom = (const float*)d_in[9];
  const float* bom = (const float*)d_in[10];
  float* out = (float*)d_out;

  cudaFuncSetAttribute(gemm_qkv,
                       cudaFuncAttributeMaxDynamicSharedMemorySize, GSMEM);
  cudaFuncSetAttribute(gemm_out128,
                       cudaFuncAttributeMaxDynamicSharedMemorySize, GSMEM2);

  Ptr6 W6;
  W6.p[0] = Wq;  W6.p[1] = Wk;  W6.p[2] = Wv;
  W6.p[3] = Wqm; W6.p[4] = Wkm; W6.p[5] = Wvm;

  prep_all<<<NALL / 256, 256>>>(W6, (const float4*)Wo, (const float4*)Wom);
  gemm_qkv<<<dim3(QKVN / 256, TOK / 128), 256, GSMEM>>>(x);
  attn_all<<<7168, 128>>>();
  gemm_out128<<<dim3(DMODEL / 128, TOK / 128), 256, GSMEM2>>>(bo, bom, x, out);
}

// round 14
// speedup vs baseline: 1.2246x; 1.0722x over previous
#include <cuda_runtime.h>
#include <cuda_bf16.h>
#include <cstdint>
#include <cstddef>

#define TOK    12288
#define DMODEL 1024
#define QKVN   6144
#define ATTN   2048

// Scratch (static device globals per harness rules)
static __device__ __nv_bfloat16 g_QKV[(size_t)TOK * QKVN];    // GEMM1 out
static __device__ __nv_bfloat16 g_ATT[(size_t)TOK * ATTN];    // attn out (GEMM2 A)
static __device__ __nv_bfloat16 g_X16[(size_t)TOK * DMODEL];  // x bf16
static __device__ __nv_bfloat16 g_W16[(size_t)QKVN * DMODEL]; // [Wq;Wk;Wv;Wqm;Wkm;Wvm]
static __device__ __nv_bfloat16 g_WO16[(size_t)DMODEL * ATTN];// row n: [Wo[n,:]|Wom[n,:]]

struct Ptr6 { const float* p[6]; };

// ---------------------------------------------------------------------------
// helpers
// ---------------------------------------------------------------------------
__device__ __forceinline__ unsigned pack_bf2(float lo, float hi) {
  unsigned d;
  asm("cvt.rn.bf16x2.f32 %0, %1, %2;" : "=r"(d) : "f"(hi), "f"(lo));
  return d;
}
__device__ __forceinline__ unsigned smem_u32(const void* p) {
  return (unsigned)__cvta_generic_to_shared(p);
}
__device__ __forceinline__ void ldm_x4(unsigned* r, unsigned addr) {
  asm volatile("ldmatrix.sync.aligned.m8n8.x4.shared.b16 {%0,%1,%2,%3}, [%4];"
               : "=r"(r[0]), "=r"(r[1]), "=r"(r[2]), "=r"(r[3]) : "r"(addr));
}
__device__ __forceinline__ void ldm_x4t(unsigned* r, unsigned addr) {
  asm volatile("ldmatrix.sync.aligned.m8n8.x4.trans.shared.b16 {%0,%1,%2,%3}, [%4];"
               : "=r"(r[0]), "=r"(r[1]), "=r"(r[2]), "=r"(r[3]) : "r"(addr));
}
__device__ __forceinline__ void mma_bf16(float* d, const unsigned* a,
                                         const unsigned* b, const float* c) {
  asm volatile(
      "mma.sync.aligned.m16n8k16.row.col.f32.bf16.bf16.f32 "
      "{%0,%1,%2,%3}, {%4,%5,%6,%7}, {%8,%9}, {%10,%11,%12,%13};"
      : "=f"(d[0]), "=f"(d[1]), "=f"(d[2]), "=f"(d[3])
      : "r"(a[0]), "r"(a[1]), "r"(a[2]), "r"(a[3]), "r"(b[0]), "r"(b[1]),
        "f"(c[0]), "f"(c[1]), "f"(c[2]), "f"(c[3]));
}
__device__ __forceinline__ void cpa16(unsigned dst, const void* src) {
  asm volatile("cp.async.cg.shared.global [%0], [%1], 16;" :: "r"(dst), "l"(src)
               : "memory");
}

// ---------------------------------------------------------------------------
// Fused prep: x conversion + weight conversions + zero-init of g_ATT mv half.
// ---------------------------------------------------------------------------
#define NX  (TOK * DMODEL / 4)          // 3145728
#define NW  (QKVN * DMODEL / 4)         // 6291456
#define NWO (DMODEL * DMODEL / 4)       // 262144
#define NZ  (TOK * 1024 / 8)            // 1572864
#define NALL (NX + NW + NWO + NZ)       // 11272192 -> 44032 blocks of 256

__global__ void prep_all(const float4* __restrict__ x, Ptr6 W,
                         const float4* __restrict__ Wo,
                         const float4* __restrict__ Wom) {
  int i = blockIdx.x * 256 + threadIdx.x;
  if (i < NX) {
    float4 v = x[i];
    ((uint2*)g_X16)[i] = make_uint2(pack_bf2(v.x, v.y), pack_bf2(v.z, v.w));
  } else if (i < NX + NW) {
    int j = i - NX;
    int row = j >> 8;
    const float4* src = (const float4*)W.p[row >> 10];
    float4 v = src[((row & 1023) << 8) + (j & 255)];
    ((uint2*)g_W16)[j] = make_uint2(pack_bf2(v.x, v.y), pack_bf2(v.z, v.w));
  } else if (i < NX + NW + NWO) {
    int j = i - NX - NW;
    int row = j >> 8, c = j & 255;
    float4 a = Wo[j], b = Wom[j];
    uint2* dst = (uint2*)g_WO16;
    dst[row * 512 + c]       = make_uint2(pack_bf2(a.x, a.y), pack_bf2(a.z, a.w));
    dst[row * 512 + 256 + c] = make_uint2(pack_bf2(b.x, b.y), pack_bf2(b.z, b.w));
  } else {
    int j = i - NX - NW - NWO;
    int row = j >> 7, c = (j & 127) * 8;
    *(uint4*)&g_ATT[(size_t)row * ATTN + 1024 + c] = make_uint4(0, 0, 0, 0);
  }
}

// ---------------------------------------------------------------------------
// 128x128 multistage bf16 GEMM core, 2 CTAs/SM co-resident (the R13 winner).
// BK=32, 4 stages (80KB smem), 256 threads, 8 warps with 64x32 warp tiles.
// MODE 0: A=g_X16  (K=1024), B=g_W16  -> bf16 g_QKV
// MODE 1: A=g_ATT  (K=2048), B=g_WO16 -> f32 Out = acc + bo + bom + X
// ---------------------------------------------------------------------------
#define BPITCH   40
#define STAGES   4
#define STG2_ELM ((128 + 128) * BPITCH)           // 10240 bf16
#define GSMEM2   (STAGES * STG2_ELM * 2)          // 81920 B

template <int K, int MODE>
__global__ __launch_bounds__(256, 2) void gemm128(
    const float* __restrict__ bo, const float* __restrict__ bom,
    const float* __restrict__ X, float* __restrict__ Out) {
  extern __shared__ __align__(16) __nv_bfloat16 sm[];
  const int tid = threadIdx.x;
  const int m0 = blockIdx.y * 128, n0 = blockIdx.x * 128;
  const __nv_bfloat16* __restrict__ A = (MODE == 0) ? g_X16 : g_ATT;
  const __nv_bfloat16* __restrict__ Bm = (MODE == 0) ? g_W16 : g_WO16;
  const int lane = tid & 31, wid = tid >> 5;
  const int wm = (wid & 1) * 64, wn = (wid >> 1) * 32;
  const int g = lane >> 2, tg = lane & 3;

  // stage loader: A 128x32 (512 chunks) + B 128x32 (512 chunks); 4/thread
  auto load_stage = [&](int k0, int s) {
    __nv_bfloat16* stg = sm + s * STG2_ELM;
#pragma unroll
    for (int j = 0; j < 4; j++) {
      const int idx = tid + j * 256;
      const int row = (idx >> 2) & 127, c = (idx & 3) * 8;
      if (idx < 512)
        cpa16(smem_u32(&stg[row * BPITCH + c]),
              &A[(size_t)(m0 + row) * K + k0 + c]);
      else
        cpa16(smem_u32(&stg[128 * BPITCH + row * BPITCH + c]),
              &Bm[(size_t)(n0 + row) * K + k0 + c]);
    }
  };

  float acc[4][4][4];
#pragma unroll
  for (int mi = 0; mi < 4; mi++)
#pragma unroll
    for (int ni = 0; ni < 4; ni++)
#pragma unroll
      for (int r = 0; r < 4; r++) acc[mi][ni][r] = 0.f;

  constexpr int NC = K / 32;
#pragma unroll
  for (int s = 0; s < STAGES - 1; s++) {
    load_stage(s * 32, s);
    asm volatile("cp.async.commit_group;" ::: "memory");
  }

#pragma unroll 1
  for (int kc = 0; kc < NC; kc++) {
    asm volatile("cp.async.wait_group %0;" :: "n"(STAGES - 2) : "memory");
    __syncthreads();
    if (kc + STAGES - 1 < NC)
      load_stage((kc + STAGES - 1) * 32, (kc + STAGES - 1) % STAGES);
    asm volatile("cp.async.commit_group;" ::: "memory");

    const int s = kc % STAGES;
    const unsigned as = smem_u32(sm + s * STG2_ELM);
    const unsigned bs = as + 128 * BPITCH * 2;
#pragma unroll
    for (int ks = 0; ks < 2; ks++) {
      const int kk = ks * 16;
      unsigned afr[4][4];
#pragma unroll
      for (int mi = 0; mi < 4; mi++)
        ldm_x4(afr[mi],
               as + ((wm + mi * 16 + (lane & 15)) * BPITCH + kk + (lane >> 4) * 8) * 2);
#pragma unroll
      for (int n2 = 0; n2 < 2; n2++) {
        unsigned bfr[4];
        ldm_x4(bfr, bs + ((wn + n2 * 16 + (lane >> 4) * 8 + (lane & 7)) * BPITCH +
                          kk + ((lane >> 3) & 1) * 8) * 2);
#pragma unroll
        for (int mi = 0; mi < 4; mi++) {
          mma_bf16(acc[mi][2 * n2], afr[mi], bfr, acc[mi][2 * n2]);
          mma_bf16(acc[mi][2 * n2 + 1], afr[mi], bfr + 2, acc[mi][2 * n2 + 1]);
        }
      }
    }
  }

#pragma unroll
  for (int mi = 0; mi < 4; mi++)
#pragma unroll
    for (int ni = 0; ni < 4; ni++) {
      const int row = m0 + wm + mi * 16 + g;
      const int col = n0 + wn + ni * 8 + 2 * tg;
      if (MODE == 0) {
        *(unsigned*)&g_QKV[(size_t)row * QKVN + col] =
            pack_bf2(acc[mi][ni][0], acc[mi][ni][1]);
        *(unsigned*)&g_QKV[(size_t)(row + 8) * QKVN + col] =
            pack_bf2(acc[mi][ni][2], acc[mi][ni][3]);
      } else {
        const float bias0 = bo[col] + bom[col];
        const float bias1 = bo[col + 1] + bom[col + 1];
        float2 x0 = *(const float2*)&X[(size_t)row * DMODEL + col];
        float2 x1 = *(const float2*)&X[(size_t)(row + 8) * DMODEL + col];
        *(float2*)&Out[(size_t)row * DMODEL + col] =
            make_float2(acc[mi][ni][0] + bias0 + x0.x, acc[mi][ni][1] + bias1 + x0.y);
        *(float2*)&Out[(size_t)(row + 8) * DMODEL + col] =
            make_float2(acc[mi][ni][2] + bias0 + x1.x, acc[mi][ni][3] + bias1 + x1.y);
      }
    }
}

// ---------------------------------------------------------------------------
// Fused flash attention (main + col + row), K/V double-buffered — R12/R13 code.
// ---------------------------------------------------------------------------
#define APITCH 72

__device__ __forceinline__ int mv_token(int bb, int j, int ij, int is_col) {
  int c = j >> 5, pos = j & 31;
  int nv = is_col ? ((c < 3) ? 2 * c : 5) : c;  // COL_IDX = {0,2,4,5}
  int s  = is_col ? (pos * 32 + ij) : (ij * 32 + pos);
  return (bb * 6 + nv) * 1024 + s;
}

__device__ __forceinline__ void fa_tile(
    unsigned qsm, unsigned ksm, unsigned vsm, int lane, int wrow,
    float& m0v, float& m1v, float& l0, float& l1, float o[8][4]) {
  const int half = (lane >> 3) & 1, quad = lane >> 4;
  float s[8][4];
#pragma unroll
  for (int nf = 0; nf < 8; nf++)
#pragma unroll
    for (int r = 0; r < 4; r++) s[nf][r] = 0.f;
#pragma unroll
  for (int kcc = 0; kcc < 4; kcc++) {
    unsigned a[4];
    ldm_x4(a, qsm + ((wrow + (lane & 15)) * APITCH + kcc * 16 + quad * 8) * 2);
#pragma unroll
    for (int n2 = 0; n2 < 4; n2++) {
      unsigned bf[4];
      ldm_x4(bf, ksm + ((n2 * 16 + quad * 8 + (lane & 7)) * APITCH + kcc * 16 + half * 8) * 2);
      mma_bf16(s[2 * n2], a, bf, s[2 * n2]);
      mma_bf16(s[2 * n2 + 1], a, bf + 2, s[2 * n2 + 1]);
    }
  }
  float mx0 = -1e30f, mx1 = -1e30f;
#pragma unroll
  for (int nf = 0; nf < 8; nf++) {
#pragma unroll
    for (int r = 0; r < 4; r++) s[nf][r] *= 0.125f;
    mx0 = fmaxf(mx0, fmaxf(s[nf][0], s[nf][1]));
    mx1 = fmaxf(mx1, fmaxf(s[nf][2], s[nf][3]));
  }
  mx0 = fmaxf(mx0, __shfl_xor_sync(0xffffffffu, mx0, 1));
  mx0 = fmaxf(mx0, __shfl_xor_sync(0xffffffffu, mx0, 2));
  mx1 = fmaxf(mx1, __shfl_xor_sync(0xffffffffu, mx1, 1));
  mx1 = fmaxf(mx1, __shfl_xor_sync(0xffffffffu, mx1, 2));
  const float nm0 = fmaxf(m0v, mx0), nm1 = fmaxf(m1v, mx1);
  const float c0 = __expf(m0v - nm0), c1 = __expf(m1v - nm1);
  m0v = nm0; m1v = nm1;
  float sum0 = 0.f, sum1 = 0.f;
  unsigned pa[4][4];
#pragma unroll
  for (int j = 0; j < 4; j++) {
    float p00 = __expf(s[2 * j][0] - nm0), p01 = __expf(s[2 * j][1] - nm0);
    float p02 = __expf(s[2 * j][2] - nm1), p03 = __expf(s[2 * j][3] - nm1);
    float p10 = __expf(s[2 * j + 1][0] - nm0), p11 = __expf(s[2 * j + 1][1] - nm0);
    float p12 = __expf(s[2 * j + 1][2] - nm1), p13 = __expf(s[2 * j + 1][3] - nm1);
    pa[j][0] = pack_bf2(p00, p01);
    pa[j][1] = pack_bf2(p02, p03);
    pa[j][2] = pack_bf2(p10, p11);
    pa[j][3] = pack_bf2(p12, p13);
    sum0 += p00 + p01 + p10 + p11;
    sum1 += p02 + p03 + p12 + p13;
  }
  sum0 += __shfl_xor_sync(0xffffffffu, sum0, 1);
  sum0 += __shfl_xor_sync(0xffffffffu, sum0, 2);
  sum1 += __shfl_xor_sync(0xffffffffu, sum1, 1);
  sum1 += __shfl_xor_sync(0xffffffffu, sum1, 2);
  l0 = l0 * c0 + sum0;
  l1 = l1 * c1 + sum1;
#pragma unroll
  for (int df = 0; df < 8; df++) {
    o[df][0] *= c0; o[df][1] *= c0; o[df][2] *= c1; o[df][3] *= c1;
  }
#pragma unroll
  for (int j = 0; j < 4; j++)
#pragma unroll
    for (int d2 = 0; d2 < 4; d2++) {
      unsigned bf[4];
      ldm_x4t(bf, vsm + ((j * 16 + half * 8 + (lane & 7)) * APITCH + d2 * 16 + quad * 8) * 2);
      mma_bf16(o[2 * d2], pa[j], bf, o[2 * d2]);
      mma_bf16(o[2 * d2 + 1], pa[j], bf + 2, o[2 * d2 + 1]);
    }
}

__global__ __launch_bounds__(128) void attn_all() {
  __shared__ __align__(16) __nv_bfloat16 Qs[64 * APITCH];
  __shared__ __align__(16) __nv_bfloat16 Ks[2][64 * APITCH];
  __shared__ __align__(16) __nv_bfloat16 Vs[2][64 * APITCH];
  const int tid = threadIdx.x, lane = tid & 31, w = tid >> 5;
  const int bx = blockIdx.x;

  const int role = (bx < 3072) ? 0 : (bx < 5120) ? 1 : 2;  // 0=main 1=col 2=row
  int qt, h, bb, ij, tb = 0;
  if (role == 0) {
    qt = bx & 15;
    const int by = bx >> 4;
    h = by & 15;
    tb = (by >> 4) << 10;
    bb = 0; ij = 0;
  } else {
    const int u = bx - (role == 1 ? 3072 : 5120);
    qt = u & 1;
    const int gy = u >> 1;
    h = gy & 15;
    ij = (gy >> 4) & 31;
    bb = gy >> 9;
  }
  const int is_col = (role == 1);
  const int colQ = (role == 0 ? 0 : 3072) + h * 64;
  const int colK = colQ + 1024;
  const int colV = colQ + 2048;
  const int ktmax = (role == 0) ? 16 : 2;

  auto ktoken = [&](int kt, int r) -> int {
    return (role == 0) ? (tb + kt * 64 + r) : mv_token(bb, kt * 64 + r, ij, is_col);
  };

  auto load_kv = [&](int kt, int s) {
#pragma unroll
    for (int i = 0; i < 8; i++) {
      const int idx = tid + i * 128;
      const int r = (idx >> 3) & 63;
      const int c8 = (idx & 7) * 8;
      const size_t trow = (size_t)ktoken(kt, r) * QKVN;
      if (idx < 512)
        cpa16(smem_u32(&Ks[s][r * APITCH + c8]), &g_QKV[trow + colK + c8]);
      else
        cpa16(smem_u32(&Vs[s][r * APITCH + c8]), &g_QKV[trow + colV + c8]);
    }
  };

#pragma unroll
  for (int i = 0; i < 4; i++) {
    int u = tid + i * 128;
    int r = u >> 3, o8 = (u & 7) * 8;
    int t = (role == 0) ? (tb + qt * 64 + r) : mv_token(bb, qt * 64 + r, ij, is_col);
    *(uint4*)&Qs[r * APITCH + o8] =
        *(const uint4*)&g_QKV[(size_t)t * QKVN + colQ + o8];
  }
  const int g = lane >> 2, tg = lane & 3;
  const int wrow = w * 16;
  float m0v = -1e30f, m1v = -1e30f, l0 = 0.f, l1 = 0.f;
  float o[8][4];
#pragma unroll
  for (int df = 0; df < 8; df++)
#pragma unroll
    for (int r = 0; r < 4; r++) o[df][r] = 0.f;
  const unsigned qsm = smem_u32(Qs);

  load_kv(0, 0);
  asm volatile("cp.async.commit_group;" ::: "memory");

#pragma unroll 1
  for (int kt = 0; kt < ktmax; kt++) {
    asm volatile("cp.async.wait_group 0;" ::: "memory");
    __syncthreads();
    if (kt + 1 < ktmax) load_kv(kt + 1, (kt + 1) & 1);
    asm volatile("cp.async.commit_group;" ::: "memory");
    const int s = kt & 1;
    fa_tile(qsm, smem_u32(Ks[s]), smem_u32(Vs[s]), lane, wrow, m0v, m1v, l0, l1, o);
    __syncthreads();
  }

  const float i0 = 1.f / l0, i1 = 1.f / l1;
  if (role == 0) {
    const int row = tb + qt * 64 + wrow + g;
#pragma unroll
    for (int df = 0; df < 8; df++) {
      const int col = h * 64 + df * 8 + 2 * tg;
      *(unsigned*)&g_ATT[(size_t)row * ATTN + col] =
          pack_bf2(o[df][0] * i0, o[df][1] * i0);
      *(unsigned*)&g_ATT[(size_t)(row + 8) * ATTN + col] =
          pack_bf2(o[df][2] * i1, o[df][3] * i1);
    }
  } else {
    const int t0 = mv_token(bb, qt * 64 + wrow + g, ij, is_col);
    const int t1 = mv_token(bb, qt * 64 + wrow + g + 8, ij, is_col);
    float wgt;
    if (is_col) {
      wgt = (qt == 0) ? 0.5f : 1.0f;
    } else {
      const int nv = 2 * qt + (w >> 1);
      wgt = (nv & 1) ? 1.0f : 0.5f;
    }
#pragma unroll
    for (int df = 0; df < 8; df++) {
      const int col = 1024 + h * 64 + df * 8 + 2 * tg;
      __nv_bfloat162 v0 = __floats2bfloat162_rn(wgt * o[df][0] * i0, wgt * o[df][1] * i0);
      __nv_bfloat162 v1 = __floats2bfloat162_rn(wgt * o[df][2] * i1, wgt * o[df][3] * i1);
      atomicAdd((__nv_bfloat162*)&g_ATT[(size_t)t0 * ATTN + col], v0);
      atomicAdd((__nv_bfloat162*)&g_ATT[(size_t)t1 * ATTN + col], v1);
    }
  }
}

// ---------------------------------------------------------------------------
extern "C" void kernel_launch(void* const* d_in, const int* in_sizes, int n_in,
                              void* d_out, int out_size) {
  (void)in_sizes; (void)n_in; (void)out_size;
  const float* x   = (const float*)d_in[0];
  const float* Wq  = (const float*)d_in[1];
  const float* Wk  = (const float*)d_in[2];
  const float* Wv  = (const float*)d_in[3];
  const float* Wo  = (const float*)d_in[4];
  const float* bo  = (const float*)d_in[5];
  const float* Wqm = (const float*)d_in[6];
  const float* Wkm = (const float*)d_in[7];
  const float* Wvm = (const float*)d_in[8];
  const float* Wom = (const float*)d_in[9];
  const float* bom = (const float*)d_in[10];
  float* out = (float*)d_out;

  cudaFuncSetAttribute(gemm128<DMODEL, 0>,
                       cudaFuncAttributeMaxDynamicSharedMemorySize, GSMEM2);
  cudaFuncSetAttribute(gemm128<ATTN, 1>,
                       cudaFuncAttributeMaxDynamicSharedMemorySize, GSMEM2);

  Ptr6 W6;
  W6.p[0] = Wq;  W6.p[1] = Wk;  W6.p[2] = Wv;
  W6.p[3] = Wqm; W6.p[4] = Wkm; W6.p[5] = Wvm;

  prep_all<<<NALL / 256, 256>>>((const float4*)x, W6,
                                (const float4*)Wo, (const float4*)Wom);
  gemm128<DMODEL, 0><<<dim3(QKVN / 128, TOK / 128), 256, GSMEM2>>>(
      nullptr, nullptr, nullptr, nullptr);
  attn_all<<<7168, 128>>>();
  gemm128<ATTN, 1><<<dim3(DMODEL / 128, TOK / 128), 256, GSMEM2>>>(
      bo, bom, x, out);
}

// round 15
// speedup vs baseline: 1.3193x; 1.0774x over previous
#include <cuda_runtime.h>
#include <cuda_bf16.h>
#include <cstdint>
#include <cstddef>

#define TOK    12288
#define DMODEL 1024
#define QKVN   6144
#define ATTN   2048

// Scratch (static device globals per harness rules)
static __device__ __nv_bfloat16 g_QKV[(size_t)TOK * QKVN];    // GEMM1 out
static __device__ __nv_bfloat16 g_ATT[(size_t)TOK * ATTN];    // attn out (GEMM2 A)
static __device__ __nv_bfloat16 g_X16[(size_t)TOK * DMODEL];  // x bf16
static __device__ __nv_bfloat16 g_W16[(size_t)QKVN * DMODEL]; // [Wq;Wk;Wv;Wqm;Wkm;Wvm]
static __device__ __nv_bfloat16 g_WO16[(size_t)DMODEL * ATTN];// row n: [Wo[n,:]|Wom[n,:]]

struct Ptr6 { const float* p[6]; };

// ---------------------------------------------------------------------------
// helpers
// ---------------------------------------------------------------------------
__device__ __forceinline__ unsigned pack_bf2(float lo, float hi) {
  unsigned d;
  asm("cvt.rn.bf16x2.f32 %0, %1, %2;" : "=r"(d) : "f"(hi), "f"(lo));
  return d;
}
__device__ __forceinline__ unsigned smem_u32(const void* p) {
  return (unsigned)__cvta_generic_to_shared(p);
}
__device__ __forceinline__ void ldm_x4(unsigned* r, unsigned addr) {
  asm volatile("ldmatrix.sync.aligned.m8n8.x4.shared.b16 {%0,%1,%2,%3}, [%4];"
               : "=r"(r[0]), "=r"(r[1]), "=r"(r[2]), "=r"(r[3]) : "r"(addr));
}
__device__ __forceinline__ void ldm_x4t(unsigned* r, unsigned addr) {
  asm volatile("ldmatrix.sync.aligned.m8n8.x4.trans.shared.b16 {%0,%1,%2,%3}, [%4];"
               : "=r"(r[0]), "=r"(r[1]), "=r"(r[2]), "=r"(r[3]) : "r"(addr));
}
__device__ __forceinline__ void mma_bf16(float* d, const unsigned* a,
                                         const unsigned* b, const float* c) {
  asm volatile(
      "mma.sync.aligned.m16n8k16.row.col.f32.bf16.bf16.f32 "
      "{%0,%1,%2,%3}, {%4,%5,%6,%7}, {%8,%9}, {%10,%11,%12,%13};"
      : "=f"(d[0]), "=f"(d[1]), "=f"(d[2]), "=f"(d[3])
      : "r"(a[0]), "r"(a[1]), "r"(a[2]), "r"(a[3]), "r"(b[0]), "r"(b[1]),
        "f"(c[0]), "f"(c[1]), "f"(c[2]), "f"(c[3]));
}
__device__ __forceinline__ void cpa16(unsigned dst, const void* src) {
  asm volatile("cp.async.cg.shared.global [%0], [%1], 16;" :: "r"(dst), "l"(src)
               : "memory");
}

// ---------------------------------------------------------------------------
// Prep: x + QKV-weight conversions only (WO conv -> attn; zero-init -> gemm1).
// ---------------------------------------------------------------------------
#define NX   (TOK * DMODEL / 4)          // 3145728
#define NW   (QKVN * DMODEL / 4)         // 6291456
#define NWO  (DMODEL * DMODEL / 4)       // 262144
#define NALL (NX + NW)                   // 9437184 -> 36864 blocks of 256

__global__ void prep_all(const float4* __restrict__ x, Ptr6 W) {
  int i = blockIdx.x * 256 + threadIdx.x;
  if (i < NX) {
    float4 v = x[i];
    ((uint2*)g_X16)[i] = make_uint2(pack_bf2(v.x, v.y), pack_bf2(v.z, v.w));
  } else {
    int j = i - NX;
    int row = j >> 8;
    const float4* src = (const float4*)W.p[row >> 10];
    float4 v = src[((row & 1023) << 8) + (j & 255)];
    ((uint2*)g_W16)[j] = make_uint2(pack_bf2(v.x, v.y), pack_bf2(v.z, v.w));
  }
}

// ---------------------------------------------------------------------------
// GEMM1: 128x128 tile, BK=32, 4 stages, 128 threads (4 warps, 64x64 warp
// tiles -> 2x A / 2x B LDSM redundancy), 2 CTAs/SM. A=g_X16, B=g_W16.
// Epilogue also zero-inits a slice of g_ATT's mv half.
// ---------------------------------------------------------------------------
#define BPITCH   40
#define STAGES   4
#define STG2_ELM ((128 + 128) * BPITCH)           // 10240 bf16
#define GSMEM2   (STAGES * STG2_ELM * 2)          // 81920 B
#define NZ_SLOTS (TOK * 1024 / 8)                 // 1572864 uint4 to zero

__global__ __launch_bounds__(128, 2) void gemm_qkv_w4() {
  extern __shared__ __align__(16) __nv_bfloat16 sm[];
  const int tid = threadIdx.x;
  const int m0 = blockIdx.y * 128, n0 = blockIdx.x * 128;
  constexpr int K = DMODEL;
  const int lane = tid & 31, wid = tid >> 5;
  const int wm = (wid & 1) * 64, wn = (wid >> 1) * 64;
  const int g = lane >> 2, tg = lane & 3;

  // stage loader: A 128x32 (512 chunks) + B 128x32 (512 chunks); 8/thread
  auto load_stage = [&](int k0, int s) {
    __nv_bfloat16* stg = sm + s * STG2_ELM;
#pragma unroll
    for (int j = 0; j < 8; j++) {
      const int idx = tid + j * 128;
      const int row = (idx >> 2) & 127, c = (idx & 3) * 8;
      if (idx < 512)
        cpa16(smem_u32(&stg[row * BPITCH + c]),
              &g_X16[(size_t)(m0 + row) * K + k0 + c]);
      else
        cpa16(smem_u32(&stg[128 * BPITCH + row * BPITCH + c]),
              &g_W16[(size_t)(n0 + row) * K + k0 + c]);
    }
  };

  float acc[4][8][4];
#pragma unroll
  for (int mi = 0; mi < 4; mi++)
#pragma unroll
    for (int ni = 0; ni < 8; ni++)
#pragma unroll
      for (int r = 0; r < 4; r++) acc[mi][ni][r] = 0.f;

  constexpr int NC = K / 32;
#pragma unroll
  for (int s = 0; s < STAGES - 1; s++) {
    load_stage(s * 32, s);
    asm volatile("cp.async.commit_group;" ::: "memory");
  }

#pragma unroll 1
  for (int kc = 0; kc < NC; kc++) {
    asm volatile("cp.async.wait_group %0;" :: "n"(STAGES - 2) : "memory");
    __syncthreads();
    if (kc + STAGES - 1 < NC)
      load_stage((kc + STAGES - 1) * 32, (kc + STAGES - 1) % STAGES);
    asm volatile("cp.async.commit_group;" ::: "memory");

    const int s = kc % STAGES;
    const unsigned as = smem_u32(sm + s * STG2_ELM);
    const unsigned bs = as + 128 * BPITCH * 2;
#pragma unroll
    for (int ks = 0; ks < 2; ks++) {
      const int kk = ks * 16;
      unsigned afr[4][4];
#pragma unroll
      for (int mi = 0; mi < 4; mi++)
        ldm_x4(afr[mi],
               as + ((wm + mi * 16 + (lane & 15)) * BPITCH + kk + (lane >> 4) * 8) * 2);
#pragma unroll
      for (int n2 = 0; n2 < 4; n2++) {
        unsigned bfr[4];
        ldm_x4(bfr, bs + ((wn + n2 * 16 + (lane >> 4) * 8 + (lane & 7)) * BPITCH +
                          kk + ((lane >> 3) & 1) * 8) * 2);
#pragma unroll
        for (int mi = 0; mi < 4; mi++) {
          mma_bf16(acc[mi][2 * n2], afr[mi], bfr, acc[mi][2 * n2]);
          mma_bf16(acc[mi][2 * n2 + 1], afr[mi], bfr + 2, acc[mi][2 * n2 + 1]);
        }
      }
    }
  }

#pragma unroll
  for (int mi = 0; mi < 4; mi++)
#pragma unroll
    for (int ni = 0; ni < 8; ni++) {
      const int row = m0 + wm + mi * 16 + g;
      const int col = n0 + wn + ni * 8 + 2 * tg;
      *(unsigned*)&g_QKV[(size_t)row * QKVN + col] =
          pack_bf2(acc[mi][ni][0], acc[mi][ni][1]);
      *(unsigned*)&g_QKV[(size_t)(row + 8) * QKVN + col] =
          pack_bf2(acc[mi][ni][2], acc[mi][ni][3]);
    }

  // zero-init slice of g_ATT mv half (needed before attn's atomicAdd)
  const size_t gt = (size_t)(blockIdx.y * gridDim.x + blockIdx.x) * 128 + tid;
  const size_t nthreads = (size_t)gridDim.x * gridDim.y * 128;
  for (size_t z = gt; z < NZ_SLOTS; z += nthreads) {
    const int row = (int)(z >> 7), c = (int)(z & 127) * 8;
    *(uint4*)&g_ATT[(size_t)row * ATTN + 1024 + c] = make_uint4(0, 0, 0, 0);
  }
}

// ---------------------------------------------------------------------------
// GEMM2 (proven R13 winner, unchanged): 128x128, 256 threads, 8 warps
// (64x32 warp tiles), 2 CTAs/SM. Out = acc + bo + bom + X.
// ---------------------------------------------------------------------------
__global__ __launch_bounds__(256, 2) void gemm_out128(
    const float* __restrict__ bo, const float* __restrict__ bom,
    const float* __restrict__ X, float* __restrict__ Out) {
  extern __shared__ __align__(16) __nv_bfloat16 sm[];
  const int tid = threadIdx.x;
  const int m0 = blockIdx.y * 128, n0 = blockIdx.x * 128;
  constexpr int K = ATTN;
  const int lane = tid & 31, wid = tid >> 5;
  const int wm = (wid & 1) * 64, wn = (wid >> 1) * 32;
  const int g = lane >> 2, tg = lane & 3;

  auto load_stage = [&](int k0, int s) {
    __nv_bfloat16* stg = sm + s * STG2_ELM;
#pragma unroll
    for (int j = 0; j < 4; j++) {
      const int idx = tid + j * 256;
      const int row = (idx >> 2) & 127, c = (idx & 3) * 8;
      if (idx < 512)
        cpa16(smem_u32(&stg[row * BPITCH + c]),
              &g_ATT[(size_t)(m0 + row) * K + k0 + c]);
      else
        cpa16(smem_u32(&stg[128 * BPITCH + row * BPITCH + c]),
              &g_WO16[(size_t)(n0 + row) * K + k0 + c]);
    }
  };

  float acc[4][4][4];
#pragma unroll
  for (int mi = 0; mi < 4; mi++)
#pragma unroll
    for (int ni = 0; ni < 4; ni++)
#pragma unroll
      for (int r = 0; r < 4; r++) acc[mi][ni][r] = 0.f;

  constexpr int NC = K / 32;
#pragma unroll
  for (int s = 0; s < STAGES - 1; s++) {
    load_stage(s * 32, s);
    asm volatile("cp.async.commit_group;" ::: "memory");
  }

#pragma unroll 1
  for (int kc = 0; kc < NC; kc++) {
    asm volatile("cp.async.wait_group %0;" :: "n"(STAGES - 2) : "memory");
    __syncthreads();
    if (kc + STAGES - 1 < NC)
      load_stage((kc + STAGES - 1) * 32, (kc + STAGES - 1) % STAGES);
    asm volatile("cp.async.commit_group;" ::: "memory");

    const int s = kc % STAGES;
    const unsigned as = smem_u32(sm + s * STG2_ELM);
    const unsigned bs = as + 128 * BPITCH * 2;
#pragma unroll
    for (int ks = 0; ks < 2; ks++) {
      const int kk = ks * 16;
      unsigned afr[4][4];
#pragma unroll
      for (int mi = 0; mi < 4; mi++)
        ldm_x4(afr[mi],
               as + ((wm + mi * 16 + (lane & 15)) * BPITCH + kk + (lane >> 4) * 8) * 2);
#pragma unroll
      for (int n2 = 0; n2 < 2; n2++) {
        unsigned bfr[4];
        ldm_x4(bfr, bs + ((wn + n2 * 16 + (lane >> 4) * 8 + (lane & 7)) * BPITCH +
                          kk + ((lane >> 3) & 1) * 8) * 2);
#pragma unroll
        for (int mi = 0; mi < 4; mi++) {
          mma_bf16(acc[mi][2 * n2], afr[mi], bfr, acc[mi][2 * n2]);
          mma_bf16(acc[mi][2 * n2 + 1], afr[mi], bfr + 2, acc[mi][2 * n2 + 1]);
        }
      }
    }
  }

#pragma unroll
  for (int mi = 0; mi < 4; mi++)
#pragma unroll
    for (int ni = 0; ni < 4; ni++) {
      const int row = m0 + wm + mi * 16 + g;
      const int col = n0 + wn + ni * 8 + 2 * tg;
      const float bias0 = bo[col] + bom[col];
      const float bias1 = bo[col + 1] + bom[col + 1];
      float2 x0 = *(const float2*)&X[(size_t)row * DMODEL + col];
      float2 x1 = *(const float2*)&X[(size_t)(row + 8) * DMODEL + col];
      *(float2*)&Out[(size_t)row * DMODEL + col] =
          make_float2(acc[mi][ni][0] + bias0 + x0.x, acc[mi][ni][1] + bias1 + x0.y);
      *(float2*)&Out[(size_t)(row + 8) * DMODEL + col] =
          make_float2(acc[mi][ni][2] + bias0 + x1.x, acc[mi][ni][3] + bias1 + x1.y);
    }
}

// ---------------------------------------------------------------------------
// Fused flash attention (main + col + row), K/V double-buffered — R12-14 code,
// plus WO-weight conversion folded into the prologue.
// ---------------------------------------------------------------------------
#define APITCH 72

__device__ __forceinline__ int mv_token(int bb, int j, int ij, int is_col) {
  int c = j >> 5, pos = j & 31;
  int nv = is_col ? ((c < 3) ? 2 * c : 5) : c;  // COL_IDX = {0,2,4,5}
  int s  = is_col ? (pos * 32 + ij) : (ij * 32 + pos);
  return (bb * 6 + nv) * 1024 + s;
}

__device__ __forceinline__ void fa_tile(
    unsigned qsm, unsigned ksm, unsigned vsm, int lane, int wrow,
    float& m0v, float& m1v, float& l0, float& l1, float o[8][4]) {
  const int half = (lane >> 3) & 1, quad = lane >> 4;
  float s[8][4];
#pragma unroll
  for (int nf = 0; nf < 8; nf++)
#pragma unroll
    for (int r = 0; r < 4; r++) s[nf][r] = 0.f;
#pragma unroll
  for (int kcc = 0; kcc < 4; kcc++) {
    unsigned a[4];
    ldm_x4(a, qsm + ((wrow + (lane & 15)) * APITCH + kcc * 16 + quad * 8) * 2);
#pragma unroll
    for (int n2 = 0; n2 < 4; n2++) {
      unsigned bf[4];
      ldm_x4(bf, ksm + ((n2 * 16 + quad * 8 + (lane & 7)) * APITCH + kcc * 16 + half * 8) * 2);
      mma_bf16(s[2 * n2], a, bf, s[2 * n2]);
      mma_bf16(s[2 * n2 + 1], a, bf + 2, s[2 * n2 + 1]);
    }
  }
  float mx0 = -1e30f, mx1 = -1e30f;
#pragma unroll
  for (int nf = 0; nf < 8; nf++) {
#pragma unroll
    for (int r = 0; r < 4; r++) s[nf][r] *= 0.125f;
    mx0 = fmaxf(mx0, fmaxf(s[nf][0], s[nf][1]));
    mx1 = fmaxf(mx1, fmaxf(s[nf][2], s[nf][3]));
  }
  mx0 = fmaxf(mx0, __shfl_xor_sync(0xffffffffu, mx0, 1));
  mx0 = fmaxf(mx0, __shfl_xor_sync(0xffffffffu, mx0, 2));
  mx1 = fmaxf(mx1, __shfl_xor_sync(0xffffffffu, mx1, 1));
  mx1 = fmaxf(mx1, __shfl_xor_sync(0xffffffffu, mx1, 2));
  const float nm0 = fmaxf(m0v, mx0), nm1 = fmaxf(m1v, mx1);
  const float c0 = __expf(m0v - nm0), c1 = __expf(m1v - nm1);
  m0v = nm0; m1v = nm1;
  float sum0 = 0.f, sum1 = 0.f;
  unsigned pa[4][4];
#pragma unroll
  for (int j = 0; j < 4; j++) {
    float p00 = __expf(s[2 * j][0] - nm0), p01 = __expf(s[2 * j][1] - nm0);
    float p02 = __expf(s[2 * j][2] - nm1), p03 = __expf(s[2 * j][3] - nm1);
    float p10 = __expf(s[2 * j + 1][0] - nm0), p11 = __expf(s[2 * j + 1][1] - nm0);
    float p12 = __expf(s[2 * j + 1][2] - nm1), p13 = __expf(s[2 * j + 1][3] - nm1);
    pa[j][0] = pack_bf2(p00, p01);
    pa[j][1] = pack_bf2(p02, p03);
    pa[j][2] = pack_bf2(p10, p11);
    pa[j][3] = pack_bf2(p12, p13);
    sum0 += p00 + p01 + p10 + p11;
    sum1 += p02 + p03 + p12 + p13;
  }
  sum0 += __shfl_xor_sync(0xffffffffu, sum0, 1);
  sum0 += __shfl_xor_sync(0xffffffffu, sum0, 2);
  sum1 += __shfl_xor_sync(0xffffffffu, sum1, 1);
  sum1 += __shfl_xor_sync(0xffffffffu, sum1, 2);
  l0 = l0 * c0 + sum0;
  l1 = l1 * c1 + sum1;
#pragma unroll
  for (int df = 0; df < 8; df++) {
    o[df][0] *= c0; o[df][1] *= c0; o[df][2] *= c1; o[df][3] *= c1;
  }
#pragma unroll
  for (int j = 0; j < 4; j++)
#pragma unroll
    for (int d2 = 0; d2 < 4; d2++) {
      unsigned bf[4];
      ldm_x4t(bf, vsm + ((j * 16 + half * 8 + (lane & 7)) * APITCH + d2 * 16 + quad * 8) * 2);
      mma_bf16(o[2 * d2], pa[j], bf, o[2 * d2]);
      mma_bf16(o[2 * d2 + 1], pa[j], bf + 2, o[2 * d2 + 1]);
    }
}

__global__ __launch_bounds__(128) void attn_all(const float4* __restrict__ Wo,
                                                const float4* __restrict__ Wom) {
  __shared__ __align__(16) __nv_bfloat16 Qs[64 * APITCH];
  __shared__ __align__(16) __nv_bfloat16 Ks[2][64 * APITCH];
  __shared__ __align__(16) __nv_bfloat16 Vs[2][64 * APITCH];
  const int tid = threadIdx.x, lane = tid & 31, w = tid >> 5;
  const int bx = blockIdx.x;

  // folded WO|Wom -> g_WO16 conversion (needed only by gemm2, next kernel)
  {
    const unsigned gw = (unsigned)bx * 128 + tid;
    if (gw < NWO) {
      const int row = gw >> 8, c = gw & 255;
      float4 a = Wo[gw], b = Wom[gw];
      uint2* dst = (uint2*)g_WO16;
      dst[row * 512 + c]       = make_uint2(pack_bf2(a.x, a.y), pack_bf2(a.z, a.w));
      dst[row * 512 + 256 + c] = make_uint2(pack_bf2(b.x, b.y), pack_bf2(b.z, b.w));
    }
  }

  const int role = (bx < 3072) ? 0 : (bx < 5120) ? 1 : 2;  // 0=main 1=col 2=row
  int qt, h, bb, ij, tb = 0;
  if (role == 0) {
    qt = bx & 15;
    const int by = bx >> 4;
    h = by & 15;
    tb = (by >> 4) << 10;
    bb = 0; ij = 0;
  } else {
    const int u = bx - (role == 1 ? 3072 : 5120);
    qt = u & 1;
    const int gy = u >> 1;
    h = gy & 15;
    ij = (gy >> 4) & 31;
    bb = gy >> 9;
  }
  const int is_col = (role == 1);
  const int colQ = (role == 0 ? 0 : 3072) + h * 64;
  const int colK = colQ + 1024;
  const int colV = colQ + 2048;
  const int ktmax = (role == 0) ? 16 : 2;

  auto ktoken = [&](int kt, int r) -> int {
    return (role == 0) ? (tb + kt * 64 + r) : mv_token(bb, kt * 64 + r, ij, is_col);
  };

  auto load_kv = [&](int kt, int s) {
#pragma unroll
    for (int i = 0; i < 8; i++) {
      const int idx = tid + i * 128;
      const int r = (idx >> 3) & 63;
      const int c8 = (idx & 7) * 8;
      const size_t trow = (size_t)ktoken(kt, r) * QKVN;
      if (idx < 512)
        cpa16(smem_u32(&Ks[s][r * APITCH + c8]), &g_QKV[trow + colK + c8]);
      else
        cpa16(smem_u32(&Vs[s][r * APITCH + c8]), &g_QKV[trow + colV + c8]);
    }
  };

#pragma unroll
  for (int i = 0; i < 4; i++) {
    int u = tid + i * 128;
    int r = u >> 3, o8 = (u & 7) * 8;
    int t = (role == 0) ? (tb + qt * 64 + r) : mv_token(bb, qt * 64 + r, ij, is_col);
    *(uint4*)&Qs[r * APITCH + o8] =
        *(const uint4*)&g_QKV[(size_t)t * QKVN + colQ + o8];
  }
  const int g = lane >> 2, tg = lane & 3;
  const int wrow = w * 16;
  float m0v = -1e30f, m1v = -1e30f, l0 = 0.f, l1 = 0.f;
  float o[8][4];
#pragma unroll
  for (int df = 0; df < 8; df++)
#pragma unroll
    for (int r = 0; r < 4; r++) o[df][r] = 0.f;
  const unsigned qsm = smem_u32(Qs);

  load_kv(0, 0);
  asm volatile("cp.async.commit_group;" ::: "memory");

#pragma unroll 1
  for (int kt = 0; kt < ktmax; kt++) {
    asm volatile("cp.async.wait_group 0;" ::: "memory");
    __syncthreads();
    if (kt + 1 < ktmax) load_kv(kt + 1, (kt + 1) & 1);
    asm volatile("cp.async.commit_group;" ::: "memory");
    const int s = kt & 1;
    fa_tile(qsm, smem_u32(Ks[s]), smem_u32(Vs[s]), lane, wrow, m0v, m1v, l0, l1, o);
    __syncthreads();
  }

  const float i0 = 1.f / l0, i1 = 1.f / l1;
  if (role == 0) {
    const int row = tb + qt * 64 + wrow + g;
#pragma unroll
    for (int df = 0; df < 8; df++) {
      const int col = h * 64 + df * 8 + 2 * tg;
      *(unsigned*)&g_ATT[(size_t)row * ATTN + col] =
          pack_bf2(o[df][0] * i0, o[df][1] * i0);
      *(unsigned*)&g_ATT[(size_t)(row + 8) * ATTN + col] =
          pack_bf2(o[df][2] * i1, o[df][3] * i1);
    }
  } else {
    const int t0 = mv_token(bb, qt * 64 + wrow + g, ij, is_col);
    const int t1 = mv_token(bb, qt * 64 + wrow + g + 8, ij, is_col);
    float wgt;
    if (is_col) {
      wgt = (qt == 0) ? 0.5f : 1.0f;
    } else {
      const int nv = 2 * qt + (w >> 1);
      wgt = (nv & 1) ? 1.0f : 0.5f;
    }
#pragma unroll
    for (int df = 0; df < 8; df++) {
      const int col = 1024 + h * 64 + df * 8 + 2 * tg;
      __nv_bfloat162 v0 = __floats2bfloat162_rn(wgt * o[df][0] * i0, wgt * o[df][1] * i0);
      __nv_bfloat162 v1 = __floats2bfloat162_rn(wgt * o[df][2] * i1, wgt * o[df][3] * i1);
      atomicAdd((__nv_bfloat162*)&g_ATT[(size_t)t0 * ATTN + col], v0);
      atomicAdd((__nv_bfloat162*)&g_ATT[(size_t)t1 * ATTN + col], v1);
    }
  }
}

// ---------------------------------------------------------------------------
extern "C" void kernel_launch(void* const* d_in, const int* in_sizes, int n_in,
                              void* d_out, int out_size) {
  (void)in_sizes; (void)n_in; (void)out_size;
  const float* x   = (const float*)d_in[0];
  const float* Wq  = (const float*)d_in[1];
  const float* Wk  = (const float*)d_in[2];
  const float* Wv  = (const float*)d_in[3];
  const float* Wo  = (const float*)d_in[4];
  const float* bo  = (const float*)d_in[5];
  const float* Wqm = (const float*)d_in[6];
  const float* Wkm = (const float*)d_in[7];
  const float* Wvm = (const float*)d_in[8];
  const float* Wom = (const float*)d_in[9];
  const float* bom = (const float*)d_in[10];
  float* out = (float*)d_out;

  cudaFuncSetAttribute(gemm_qkv_w4,
                       cudaFuncAttributeMaxDynamicSharedMemorySize, GSMEM2);
  cudaFuncSetAttribute(gemm_out128,
                       cudaFuncAttributeMaxDynamicSharedMemorySize, GSMEM2);

  Ptr6 W6;
  W6.p[0] = Wq;  W6.p[1] = Wk;  W6.p[2] = Wv;
  W6.p[3] = Wqm; W6.p[4] = Wkm; W6.p[5] = Wvm;

  prep_all<<<NALL / 256, 256>>>((const float4*)x, W6);
  gemm_qkv_w4<<<dim3(QKVN / 128, TOK / 128), 128, GSMEM2>>>();
  attn_all<<<7168, 128>>>((const float4*)Wo, (const float4*)Wom);
  gemm_out128<<<dim3(DMODEL / 128, TOK / 128), 256, GSMEM2>>>(bo, bom, x, out);
}

// round 16
// speedup vs baseline: 1.3316x; 1.0094x over previous
#include <cuda_runtime.h>
#include <cuda_bf16.h>
#include <cstdint>
#include <cstddef>

#define TOK    12288
#define DMODEL 1024
#define QKVN   6144
#define ATTN   2048

// Scratch (static device globals per harness rules)
static __device__ __nv_bfloat16 g_QKV[(size_t)TOK * QKVN];    // GEMM1 out
static __device__ __nv_bfloat16 g_ATT[(size_t)TOK * ATTN];    // attn out (GEMM2 A)
static __device__ __nv_bfloat16 g_X16[(size_t)TOK * DMODEL];  // x bf16
static __device__ __nv_bfloat16 g_W16[(size_t)QKVN * DMODEL]; // [Wq;Wk;Wv;Wqm;Wkm;Wvm]
static __device__ __nv_bfloat16 g_WO16[(size_t)DMODEL * ATTN];// row n: [Wo[n,:]|Wom[n,:]]

struct Ptr6 { const float* p[6]; };

// ---------------------------------------------------------------------------
// helpers
// ---------------------------------------------------------------------------
__device__ __forceinline__ unsigned pack_bf2(float lo, float hi) {
  unsigned d;
  asm("cvt.rn.bf16x2.f32 %0, %1, %2;" : "=r"(d) : "f"(hi), "f"(lo));
  return d;
}
__device__ __forceinline__ unsigned smem_u32(const void* p) {
  return (unsigned)__cvta_generic_to_shared(p);
}
__device__ __forceinline__ void ldm_x4(unsigned* r, unsigned addr) {
  asm volatile("ldmatrix.sync.aligned.m8n8.x4.shared.b16 {%0,%1,%2,%3}, [%4];"
               : "=r"(r[0]), "=r"(r[1]), "=r"(r[2]), "=r"(r[3]) : "r"(addr));
}
__device__ __forceinline__ void ldm_x4t(unsigned* r, unsigned addr) {
  asm volatile("ldmatrix.sync.aligned.m8n8.x4.trans.shared.b16 {%0,%1,%2,%3}, [%4];"
               : "=r"(r[0]), "=r"(r[1]), "=r"(r[2]), "=r"(r[3]) : "r"(addr));
}
__device__ __forceinline__ void mma_bf16(float* d, const unsigned* a,
                                         const unsigned* b, const float* c) {
  asm volatile(
      "mma.sync.aligned.m16n8k16.row.col.f32.bf16.bf16.f32 "
      "{%0,%1,%2,%3}, {%4,%5,%6,%7}, {%8,%9}, {%10,%11,%12,%13};"
      : "=f"(d[0]), "=f"(d[1]), "=f"(d[2]), "=f"(d[3])
      : "r"(a[0]), "r"(a[1]), "r"(a[2]), "r"(a[3]), "r"(b[0]), "r"(b[1]),
        "f"(c[0]), "f"(c[1]), "f"(c[2]), "f"(c[3]));
}
__device__ __forceinline__ void cpa16(unsigned dst, const void* src) {
  asm volatile("cp.async.cg.shared.global [%0], [%1], 16;" :: "r"(dst), "l"(src)
               : "memory");
}

// ---------------------------------------------------------------------------
// Prep: x + QKV-weight conversions only (WO conv -> attn; zero-init -> gemm1).
// ---------------------------------------------------------------------------
#define NX   (TOK * DMODEL / 4)          // 3145728
#define NW   (QKVN * DMODEL / 4)         // 6291456
#define NWO  (DMODEL * DMODEL / 4)       // 262144
#define NALL (NX + NW)                   // 9437184 -> 36864 blocks of 256

__global__ void prep_all(const float4* __restrict__ x, Ptr6 W) {
  int i = blockIdx.x * 256 + threadIdx.x;
  if (i < NX) {
    float4 v = x[i];
    ((uint2*)g_X16)[i] = make_uint2(pack_bf2(v.x, v.y), pack_bf2(v.z, v.w));
  } else {
    int j = i - NX;
    int row = j >> 8;
    const float4* src = (const float4*)W.p[row >> 10];
    float4 v = src[((row & 1023) << 8) + (j & 255)];
    ((uint2*)g_W16)[j] = make_uint2(pack_bf2(v.x, v.y), pack_bf2(v.z, v.w));
  }
}

// ---------------------------------------------------------------------------
// 128x128 multistage bf16 GEMM core: 4 warps (64x64 warp tiles -> 2x/2x LDSM
// redundancy), BK=32, 4 stages, 2 CTAs/SM. The R15-confirmed smem-BW-optimal
// shape, now used for BOTH GEMMs.
// MODE 0: A=g_X16 (K=1024), B=g_W16  -> bf16 g_QKV (+ g_ATT mv-half zero-init)
// MODE 1: A=g_ATT (K=2048), B=g_WO16 -> f32 Out = acc + bo + bom + X
// ---------------------------------------------------------------------------
#define BPITCH   40
#define STAGES   4
#define STG2_ELM ((128 + 128) * BPITCH)           // 10240 bf16
#define GSMEM2   (STAGES * STG2_ELM * 2)          // 81920 B
#define NZ_SLOTS (TOK * 1024 / 8)                 // 1572864 uint4 to zero

template <int K, int MODE>
__global__ __launch_bounds__(128, 2) void gemm_w4(
    const float* __restrict__ bo, const float* __restrict__ bom,
    const float* __restrict__ X, float* __restrict__ Out) {
  extern __shared__ __align__(16) __nv_bfloat16 sm[];
  const int tid = threadIdx.x;
  const int m0 = blockIdx.y * 128, n0 = blockIdx.x * 128;
  const __nv_bfloat16* __restrict__ A = (MODE == 0) ? g_X16 : g_ATT;
  const __nv_bfloat16* __restrict__ Bm = (MODE == 0) ? g_W16 : g_WO16;
  const int lane = tid & 31, wid = tid >> 5;
  const int wm = (wid & 1) * 64, wn = (wid >> 1) * 64;
  const int g = lane >> 2, tg = lane & 3;

  // stage loader: A 128x32 (512 chunks) + B 128x32 (512 chunks); 8/thread
  auto load_stage = [&](int k0, int s) {
    __nv_bfloat16* stg = sm + s * STG2_ELM;
#pragma unroll
    for (int j = 0; j < 8; j++) {
      const int idx = tid + j * 128;
      const int row = (idx >> 2) & 127, c = (idx & 3) * 8;
      if (idx < 512)
        cpa16(smem_u32(&stg[row * BPITCH + c]),
              &A[(size_t)(m0 + row) * K + k0 + c]);
      else
        cpa16(smem_u32(&stg[128 * BPITCH + row * BPITCH + c]),
              &Bm[(size_t)(n0 + row) * K + k0 + c]);
    }
  };

  float acc[4][8][4];
#pragma unroll
  for (int mi = 0; mi < 4; mi++)
#pragma unroll
    for (int ni = 0; ni < 8; ni++)
#pragma unroll
      for (int r = 0; r < 4; r++) acc[mi][ni][r] = 0.f;

  constexpr int NC = K / 32;
#pragma unroll
  for (int s = 0; s < STAGES - 1; s++) {
    load_stage(s * 32, s);
    asm volatile("cp.async.commit_group;" ::: "memory");
  }

#pragma unroll 1
  for (int kc = 0; kc < NC; kc++) {
    asm volatile("cp.async.wait_group %0;" :: "n"(STAGES - 2) : "memory");
    __syncthreads();
    if (kc + STAGES - 1 < NC)
      load_stage((kc + STAGES - 1) * 32, (kc + STAGES - 1) % STAGES);
    asm volatile("cp.async.commit_group;" ::: "memory");

    const int s = kc % STAGES;
    const unsigned as = smem_u32(sm + s * STG2_ELM);
    const unsigned bs = as + 128 * BPITCH * 2;
#pragma unroll
    for (int ks = 0; ks < 2; ks++) {
      const int kk = ks * 16;
      unsigned afr[4][4];
#pragma unroll
      for (int mi = 0; mi < 4; mi++)
        ldm_x4(afr[mi],
               as + ((wm + mi * 16 + (lane & 15)) * BPITCH + kk + (lane >> 4) * 8) * 2);
#pragma unroll
      for (int n2 = 0; n2 < 4; n2++) {
        unsigned bfr[4];
        ldm_x4(bfr, bs + ((wn + n2 * 16 + (lane >> 4) * 8 + (lane & 7)) * BPITCH +
                          kk + ((lane >> 3) & 1) * 8) * 2);
#pragma unroll
        for (int mi = 0; mi < 4; mi++) {
          mma_bf16(acc[mi][2 * n2], afr[mi], bfr, acc[mi][2 * n2]);
          mma_bf16(acc[mi][2 * n2 + 1], afr[mi], bfr + 2, acc[mi][2 * n2 + 1]);
        }
      }
    }
  }

#pragma unroll
  for (int mi = 0; mi < 4; mi++)
#pragma unroll
    for (int ni = 0; ni < 8; ni++) {
      const int row = m0 + wm + mi * 16 + g;
      const int col = n0 + wn + ni * 8 + 2 * tg;
      if (MODE == 0) {
        *(unsigned*)&g_QKV[(size_t)row * QKVN + col] =
            pack_bf2(acc[mi][ni][0], acc[mi][ni][1]);
        *(unsigned*)&g_QKV[(size_t)(row + 8) * QKVN + col] =
            pack_bf2(acc[mi][ni][2], acc[mi][ni][3]);
      } else {
        const float bias0 = bo[col] + bom[col];
        const float bias1 = bo[col + 1] + bom[col + 1];
        float2 x0 = *(const float2*)&X[(size_t)row * DMODEL + col];
        float2 x1 = *(const float2*)&X[(size_t)(row + 8) * DMODEL + col];
        *(float2*)&Out[(size_t)row * DMODEL + col] =
            make_float2(acc[mi][ni][0] + bias0 + x0.x, acc[mi][ni][1] + bias1 + x0.y);
        *(float2*)&Out[(size_t)(row + 8) * DMODEL + col] =
            make_float2(acc[mi][ni][2] + bias0 + x1.x, acc[mi][ni][3] + bias1 + x1.y);
      }
    }

  if (MODE == 0) {
    // zero-init slice of g_ATT mv half (needed before attn's atomicAdd)
    const size_t gt = (size_t)(blockIdx.y * gridDim.x + blockIdx.x) * 128 + tid;
    const size_t nthreads = (size_t)gridDim.x * gridDim.y * 128;
    for (size_t z = gt; z < NZ_SLOTS; z += nthreads) {
      const int row = (int)(z >> 7), c = (int)(z & 127) * 8;
      *(uint4*)&g_ATT[(size_t)row * ATTN + 1024 + c] = make_uint4(0, 0, 0, 0);
    }
  }
}

// ---------------------------------------------------------------------------
// Fused flash attention (main + col + row), K/V double-buffered — R15 code,
// WO-weight conversion folded into the prologue.
// ---------------------------------------------------------------------------
#define APITCH 72

__device__ __forceinline__ int mv_token(int bb, int j, int ij, int is_col) {
  int c = j >> 5, pos = j & 31;
  int nv = is_col ? ((c < 3) ? 2 * c : 5) : c;  // COL_IDX = {0,2,4,5}
  int s  = is_col ? (pos * 32 + ij) : (ij * 32 + pos);
  return (bb * 6 + nv) * 1024 + s;
}

__device__ __forceinline__ void fa_tile(
    unsigned qsm, unsigned ksm, unsigned vsm, int lane, int wrow,
    float& m0v, float& m1v, float& l0, float& l1, float o[8][4]) {
  const int half = (lane >> 3) & 1, quad = lane >> 4;
  float s[8][4];
#pragma unroll
  for (int nf = 0; nf < 8; nf++)
#pragma unroll
    for (int r = 0; r < 4; r++) s[nf][r] = 0.f;
#pragma unroll
  for (int kcc = 0; kcc < 4; kcc++) {
    unsigned a[4];
    ldm_x4(a, qsm + ((wrow + (lane & 15)) * APITCH + kcc * 16 + quad * 8) * 2);
#pragma unroll
    for (int n2 = 0; n2 < 4; n2++) {
      unsigned bf[4];
      ldm_x4(bf, ksm + ((n2 * 16 + quad * 8 + (lane & 7)) * APITCH + kcc * 16 + half * 8) * 2);
      mma_bf16(s[2 * n2], a, bf, s[2 * n2]);
      mma_bf16(s[2 * n2 + 1], a, bf + 2, s[2 * n2 + 1]);
    }
  }
  float mx0 = -1e30f, mx1 = -1e30f;
#pragma unroll
  for (int nf = 0; nf < 8; nf++) {
#pragma unroll
    for (int r = 0; r < 4; r++) s[nf][r] *= 0.125f;
    mx0 = fmaxf(mx0, fmaxf(s[nf][0], s[nf][1]));
    mx1 = fmaxf(mx1, fmaxf(s[nf][2], s[nf][3]));
  }
  mx0 = fmaxf(mx0, __shfl_xor_sync(0xffffffffu, mx0, 1));
  mx0 = fmaxf(mx0, __shfl_xor_sync(0xffffffffu, mx0, 2));
  mx1 = fmaxf(mx1, __shfl_xor_sync(0xffffffffu, mx1, 1));
  mx1 = fmaxf(mx1, __shfl_xor_sync(0xffffffffu, mx1, 2));
  const float nm0 = fmaxf(m0v, mx0), nm1 = fmaxf(m1v, mx1);
  const float c0 = __expf(m0v - nm0), c1 = __expf(m1v - nm1);
  m0v = nm0; m1v = nm1;
  float sum0 = 0.f, sum1 = 0.f;
  unsigned pa[4][4];
#pragma unroll
  for (int j = 0; j < 4; j++) {
    float p00 = __expf(s[2 * j][0] - nm0), p01 = __expf(s[2 * j][1] - nm0);
    float p02 = __expf(s[2 * j][2] - nm1), p03 = __expf(s[2 * j][3] - nm1);
    float p10 = __expf(s[2 * j + 1][0] - nm0), p11 = __expf(s[2 * j + 1][1] - nm0);
    float p12 = __expf(s[2 * j + 1][2] - nm1), p13 = __expf(s[2 * j + 1][3] - nm1);
    pa[j][0] = pack_bf2(p00, p01);
    pa[j][1] = pack_bf2(p02, p03);
    pa[j][2] = pack_bf2(p10, p11);
    pa[j][3] = pack_bf2(p12, p13);
    sum0 += p00 + p01 + p10 + p11;
    sum1 += p02 + p03 + p12 + p13;
  }
  sum0 += __shfl_xor_sync(0xffffffffu, sum0, 1);
  sum0 += __shfl_xor_sync(0xffffffffu, sum0, 2);
  sum1 += __shfl_xor_sync(0xffffffffu, sum1, 1);
  sum1 += __shfl_xor_sync(0xffffffffu, sum1, 2);
  l0 = l0 * c0 + sum0;
  l1 = l1 * c1 + sum1;
#pragma unroll
  for (int df = 0; df < 8; df++) {
    o[df][0] *= c0; o[df][1] *= c0; o[df][2] *= c1; o[df][3] *= c1;
  }
#pragma unroll
  for (int j = 0; j < 4; j++)
#pragma unroll
    for (int d2 = 0; d2 < 4; d2++) {
      unsigned bf[4];
      ldm_x4t(bf, vsm + ((j * 16 + half * 8 + (lane & 7)) * APITCH + d2 * 16 + quad * 8) * 2);
      mma_bf16(o[2 * d2], pa[j], bf, o[2 * d2]);
      mma_bf16(o[2 * d2 + 1], pa[j], bf + 2, o[2 * d2 + 1]);
    }
}

__global__ __launch_bounds__(128) void attn_all(const float4* __restrict__ Wo,
                                                const float4* __restrict__ Wom) {
  __shared__ __align__(16) __nv_bfloat16 Qs[64 * APITCH];
  __shared__ __align__(16) __nv_bfloat16 Ks[2][64 * APITCH];
  __shared__ __align__(16) __nv_bfloat16 Vs[2][64 * APITCH];
  const int tid = threadIdx.x, lane = tid & 31, w = tid >> 5;
  const int bx = blockIdx.x;

  // folded WO|Wom -> g_WO16 conversion (consumed by gemm2, next kernel)
  {
    const unsigned gw = (unsigned)bx * 128 + tid;
    if (gw < NWO) {
      const int row = gw >> 8, c = gw & 255;
      float4 a = Wo[gw], b = Wom[gw];
      uint2* dst = (uint2*)g_WO16;
      dst[row * 512 + c]       = make_uint2(pack_bf2(a.x, a.y), pack_bf2(a.z, a.w));
      dst[row * 512 + 256 + c] = make_uint2(pack_bf2(b.x, b.y), pack_bf2(b.z, b.w));
    }
  }

  const int role = (bx < 3072) ? 0 : (bx < 5120) ? 1 : 2;  // 0=main 1=col 2=row
  int qt, h, bb, ij, tb = 0;
  if (role == 0) {
    qt = bx & 15;
    const int by = bx >> 4;
    h = by & 15;
    tb = (by >> 4) << 10;
    bb = 0; ij = 0;
  } else {
    const int u = bx - (role == 1 ? 3072 : 5120);
    qt = u & 1;
    const int gy = u >> 1;
    h = gy & 15;
    ij = (gy >> 4) & 31;
    bb = gy >> 9;
  }
  const int is_col = (role == 1);
  const int colQ = (role == 0 ? 0 : 3072) + h * 64;
  const int colK = colQ + 1024;
  const int colV = colQ + 2048;
  const int ktmax = (role == 0) ? 16 : 2;

  auto ktoken = [&](int kt, int r) -> int {
    return (role == 0) ? (tb + kt * 64 + r) : mv_token(bb, kt * 64 + r, ij, is_col);
  };

  auto load_kv = [&](int kt, int s) {
#pragma unroll
    for (int i = 0; i < 8; i++) {
      const int idx = tid + i * 128;
      const int r = (idx >> 3) & 63;
      const int c8 = (idx & 7) * 8;
      const size_t trow = (size_t)ktoken(kt, r) * QKVN;
      if (idx < 512)
        cpa16(smem_u32(&Ks[s][r * APITCH + c8]), &g_QKV[trow + colK + c8]);
      else
        cpa16(smem_u32(&Vs[s][r * APITCH + c8]), &g_QKV[trow + colV + c8]);
    }
  };

#pragma unroll
  for (int i = 0; i < 4; i++) {
    int u = tid + i * 128;
    int r = u >> 3, o8 = (u & 7) * 8;
    int t = (role == 0) ? (tb + qt * 64 + r) : mv_token(bb, qt * 64 + r, ij, is_col);
    *(uint4*)&Qs[r * APITCH + o8] =
        *(const uint4*)&g_QKV[(size_t)t * QKVN + colQ + o8];
  }
  const int g = lane >> 2, tg = lane & 3;
  const int wrow = w * 16;
  float m0v = -1e30f, m1v = -1e30f, l0 = 0.f, l1 = 0.f;
  float o[8][4];
#pragma unroll
  for (int df = 0; df < 8; df++)
#pragma unroll
    for (int r = 0; r < 4; r++) o[df][r] = 0.f;
  const unsigned qsm = smem_u32(Qs);

  load_kv(0, 0);
  asm volatile("cp.async.commit_group;" ::: "memory");

#pragma unroll 1
  for (int kt = 0; kt < ktmax; kt++) {
    asm volatile("cp.async.wait_group 0;" ::: "memory");
    __syncthreads();
    if (kt + 1 < ktmax) load_kv(kt + 1, (kt + 1) & 1);
    asm volatile("cp.async.commit_group;" ::: "memory");
    const int s = kt & 1;
    fa_tile(qsm, smem_u32(Ks[s]), smem_u32(Vs[s]), lane, wrow, m0v, m1v, l0, l1, o);
    __syncthreads();
  }

  const float i0 = 1.f / l0, i1 = 1.f / l1;
  if (role == 0) {
    const int row = tb + qt * 64 + wrow + g;
#pragma unroll
    for (int df = 0; df < 8; df++) {
      const int col = h * 64 + df * 8 + 2 * tg;
      *(unsigned*)&g_ATT[(size_t)row * ATTN + col] =
          pack_bf2(o[df][0] * i0, o[df][1] * i0);
      *(unsigned*)&g_ATT[(size_t)(row + 8) * ATTN + col] =
          pack_bf2(o[df][2] * i1, o[df][3] * i1);
    }
  } else {
    const int t0 = mv_token(bb, qt * 64 + wrow + g, ij, is_col);
    const int t1 = mv_token(bb, qt * 64 + wrow + g + 8, ij, is_col);
    float wgt;
    if (is_col) {
      wgt = (qt == 0) ? 0.5f : 1.0f;
    } else {
      const int nv = 2 * qt + (w >> 1);
      wgt = (nv & 1) ? 1.0f : 0.5f;
    }
#pragma unroll
    for (int df = 0; df < 8; df++) {
      const int col = 1024 + h * 64 + df * 8 + 2 * tg;
      __nv_bfloat162 v0 = __floats2bfloat162_rn(wgt * o[df][0] * i0, wgt * o[df][1] * i0);
      __nv_bfloat162 v1 = __floats2bfloat162_rn(wgt * o[df][2] * i1, wgt * o[df][3] * i1);
      atomicAdd((__nv_bfloat162*)&g_ATT[(size_t)t0 * ATTN + col], v0);
      atomicAdd((__nv_bfloat162*)&g_ATT[(size_t)t1 * ATTN + col], v1);
    }
  }
}

// ---------------------------------------------------------------------------
extern "C" void kernel_launch(void* const* d_in, const int* in_sizes, int n_in,
                              void* d_out, int out_size) {
  (void)in_sizes; (void)n_in; (void)out_size;
  const float* x   = (const float*)d_in[0];
  const float* Wq  = (const float*)d_in[1];
  const float* Wk  = (const float*)d_in[2];
  const float* Wv  = (const float*)d_in[3];
  const float* Wo  = (const float*)d_in[4];
  const float* bo  = (const float*)d_in[5];
  const float* Wqm = (const float*)d_in[6];
  const float* Wkm = (const float*)d_in[7];
  const float* Wvm = (const float*)d_in[8];
  const float* Wom = (const float*)d_in[9];
  const float* bom = (const float*)d_in[10];
  float* out = (float*)d_out;

  cudaFuncSetAttribute(gemm_w4<DMODEL, 0>,
                       cudaFuncAttributeMaxDynamicSharedMemorySize, GSMEM2);
  cudaFuncSetAttribute(gemm_w4<ATTN, 1>,
                       cudaFuncAttributeMaxDynamicSharedMemorySize, GSMEM2);

  Ptr6 W6;
  W6.p[0] = Wq;  W6.p[1] = Wk;  W6.p[2] = Wv;
  W6.p[3] = Wqm; W6.p[4] = Wkm; W6.p[5] = Wvm;

  prep_all<<<NALL / 256, 256>>>((const float4*)x, W6);
  gemm_w4<DMODEL, 0><<<dim3(QKVN / 128, TOK / 128), 128, GSMEM2>>>(
      nullptr, nullptr, nullptr, nullptr);
  attn_all<<<7168, 128>>>((const float4*)Wo, (const float4*)Wom);
  gemm_w4<ATTN, 1><<<dim3(DMODEL / 128, TOK / 128), 128, GSMEM2>>>(
      bo, bom, x, out);
}